// round 1
// baseline (speedup 1.0000x reference)
#include <cuda_runtime.h>
#include <cstdint>
#include <cstddef>

// ---------------------------------------------------------------------------
// Dipole head: two gated blocks + segment sums.
// Round-0 baseline: fp32 multi-kernel pipeline, packed f32x2 FMAs in the GEMM.
// ---------------------------------------------------------------------------

#define NA_MAX 200000

// Global scratch (device globals are the sanctioned scratch mechanism).
__device__ float g_vmix[(size_t)3 * NA_MAX * 512];   // block-1 vmix (3N x 512)
__device__ float g_vvn [(size_t)NA_MAX * 256];       // ||vV|| per atom (N x 256)
__device__ float g_h   [(size_t)NA_MAX * 256];       // h (reused for h2)
__device__ float g_s1  [(size_t)NA_MAX * 256];       // block-1 s_out (silu'd)
__device__ float g_gate[(size_t)NA_MAX * 256];       // block-1 gate
__device__ float g_vvn2[NA_MAX];                     // block-2 ||vV2||
__device__ float g_vw2 [(size_t)3 * NA_MAX];         // block-2 vW (N x 3)

__device__ __forceinline__ float silu_f(float x) {
    return x / (1.0f + __expf(-x));
}

// Packed fp32x2 FMA (FFMA2) — 2x FFMA throughput on sm_103a.
__device__ __forceinline__ unsigned long long fma2(unsigned long long a,
                                                   unsigned long long b,
                                                   unsigned long long c) {
    unsigned long long d;
    asm("fma.rn.f32x2 %0, %1, %2, %3;" : "=l"(d) : "l"(a), "l"(b), "l"(c));
    return d;
}
__device__ __forceinline__ unsigned long long pack_dup(float x) {
    unsigned long long d;
    asm("mov.b64 %0, {%1, %1};" : "=l"(d) : "f"(x));
    return d;
}
__device__ __forceinline__ unsigned long long pack2f(float x, float y) {
    unsigned long long d;
    asm("mov.b64 %0, {%1, %2};" : "=l"(d) : "f"(x), "f"(y));
    return d;
}
__device__ __forceinline__ float2 unpack2(unsigned long long v) {
    float2 r;
    asm("mov.b64 {%0, %1}, %2;" : "=f"(r.x), "=f"(r.y) : "l"(v));
    return r;
}

// ---------------------------------------------------------------------------
// Generic SGEMM: C = epilogue(A @ B)
//   A: row-major, lda == 256 for every source in this network.
//   Optional second A source (A1) starting at k == ksplit (virtual concat).
//   B: row-major [K, N].
// Tiles: BM=BN=128, BK=16; 256 threads; 8x8 micro-tile as 8x4 f32x2 pairs.
// Epilogues:
//   0: plain store to C0 (ldc = N)
//   1: silu(v + bias[n]) -> C0 (ldc = 256)
//   2: n<256: silu(v+bias)->C0 ; n>=256: (v+bias)->C1  (both ldc = 256)
//   3: silu(v + u[m]*vrow[n] + bias[n]) -> C0 (ldc = 256)
// ---------------------------------------------------------------------------
struct GP {
    const float* A0;
    const float* A1;
    int          ksplit;
    const float* B;
    int M, N, K;
    float*       C0;
    float*       C1;
    const float* bias;
    const float* u;     // per-row scalar (rank-1 term)
    const float* vrow;  // per-col vector (rank-1 term)
};

template <int EPI>
__global__ __launch_bounds__(256) void gemm_k(GP p) {
    __shared__ __align__(16) float As[2][16][128];
    __shared__ __align__(16) float Bs[2][16][128];

    const int tid  = threadIdx.x;
    const int tx   = tid & 15;
    const int ty   = tid >> 4;
    const int row0 = blockIdx.y * 128;
    const int col0 = blockIdx.x * 128;

    float4 aR[2], bR[2];

    auto loadA = [&](int kt) {
#pragma unroll
        for (int i = 0; i < 2; i++) {
            int idx = i * 256 + tid;
            int m = idx >> 2, g = idx & 3;
            int gm = row0 + m;
            int k  = kt + 4 * g;
            if (gm < p.M) {
                const float* src;
                if (k < p.ksplit) src = p.A0 + (size_t)gm * 256 + k;
                else              src = p.A1 + (size_t)gm * 256 + (k - p.ksplit);
                aR[i] = *reinterpret_cast<const float4*>(src);
            } else {
                aR[i] = make_float4(0.f, 0.f, 0.f, 0.f);
            }
        }
    };
    auto loadB = [&](int kt) {
#pragma unroll
        for (int i = 0; i < 2; i++) {
            int idx = i * 256 + tid;
            int k = idx >> 5, g = idx & 31;
            bR[i] = *reinterpret_cast<const float4*>(
                p.B + (size_t)(kt + k) * p.N + col0 + 4 * g);
        }
    };
    auto stage = [&](int buf) {
#pragma unroll
        for (int i = 0; i < 2; i++) {
            int idx = i * 256 + tid;
            int m = idx >> 2, g = idx & 3;
            As[buf][4 * g + 0][m] = aR[i].x;
            As[buf][4 * g + 1][m] = aR[i].y;
            As[buf][4 * g + 2][m] = aR[i].z;
            As[buf][4 * g + 3][m] = aR[i].w;
            int k = idx >> 5, gn = (idx & 31) * 4;
            *reinterpret_cast<float4*>(&Bs[buf][k][gn]) = bR[i];
        }
    };

    unsigned long long acc[8][4];
#pragma unroll
    for (int i = 0; i < 8; i++)
#pragma unroll
        for (int j = 0; j < 4; j++) acc[i][j] = 0ull;

    loadA(0);
    loadB(0);
    stage(0);
    __syncthreads();

    const int nk = p.K / 16;
    for (int t = 0; t < nk; t++) {
        const int buf = t & 1;
        if (t + 1 < nk) {
            loadA((t + 1) * 16);
            loadB((t + 1) * 16);
        }
#pragma unroll
        for (int k = 0; k < 16; k++) {
            float4 a0 = *reinterpret_cast<const float4*>(&As[buf][k][ty * 4]);
            float4 a1 = *reinterpret_cast<const float4*>(&As[buf][k][ty * 4 + 64]);
            float4 b0 = *reinterpret_cast<const float4*>(&Bs[buf][k][tx * 4]);
            float4 b1 = *reinterpret_cast<const float4*>(&Bs[buf][k][tx * 4 + 64]);
            unsigned long long bp0 = pack2f(b0.x, b0.y);
            unsigned long long bp1 = pack2f(b0.z, b0.w);
            unsigned long long bp2 = pack2f(b1.x, b1.y);
            unsigned long long bp3 = pack2f(b1.z, b1.w);
            float av[8] = {a0.x, a0.y, a0.z, a0.w, a1.x, a1.y, a1.z, a1.w};
#pragma unroll
            for (int im = 0; im < 8; im++) {
                unsigned long long ap = pack_dup(av[im]);
                acc[im][0] = fma2(ap, bp0, acc[im][0]);
                acc[im][1] = fma2(ap, bp1, acc[im][1]);
                acc[im][2] = fma2(ap, bp2, acc[im][2]);
                acc[im][3] = fma2(ap, bp3, acc[im][3]);
            }
        }
        __syncthreads();
        if (t + 1 < nk) {
            stage(buf ^ 1);
            __syncthreads();
        }
    }

// Epilogue
#pragma unroll
    for (int im = 0; im < 8; im++) {
        int m = row0 + ty * 4 + (im & 3) + (im >> 2) * 64;
        if (m >= p.M) continue;
#pragma unroll
        for (int jn = 0; jn < 4; jn++) {
            float2 v = unpack2(acc[im][jn]);
            int n = col0 + tx * 4 + (jn & 1) * 2 + (jn >> 1) * 64;
            if (EPI == 0) {
                *reinterpret_cast<float2*>(p.C0 + (size_t)m * p.N + n) = v;
            } else if (EPI == 1) {
                v.x = silu_f(v.x + p.bias[n]);
                v.y = silu_f(v.y + p.bias[n + 1]);
                *reinterpret_cast<float2*>(p.C0 + (size_t)m * 256 + n) = v;
            } else if (EPI == 2) {
                v.x += p.bias[n];
                v.y += p.bias[n + 1];
                if (n < 256) {
                    v.x = silu_f(v.x);
                    v.y = silu_f(v.y);
                    *reinterpret_cast<float2*>(p.C0 + (size_t)m * 256 + n) = v;
                } else {
                    *reinterpret_cast<float2*>(p.C1 + (size_t)m * 256 + (n - 256)) = v;
                }
            } else {
                float um = p.u[m];
                v.x = silu_f(v.x + um * p.vrow[n]     + p.bias[n]);
                v.y = silu_f(v.y + um * p.vrow[n + 1] + p.bias[n + 1]);
                *reinterpret_cast<float2*>(p.C0 + (size_t)m * 256 + n) = v;
            }
        }
    }
}

// ---------------------------------------------------------------------------
// vVn[m, o] = || vmix[m, :, o] ||  over the 3 spatial components (cols 0..255)
// ---------------------------------------------------------------------------
__global__ void vvn_kernel(const float* __restrict__ vmix,
                           float* __restrict__ vvn, int natoms) {
    int m = blockIdx.x;
    int o = threadIdx.x;
    if (m >= natoms) return;
    const float* r = vmix + (size_t)3 * m * 512 + o;
    float a = r[0], b = r[512], c = r[1024];
    vvn[(size_t)m * 256 + o] = sqrtf(a * a + b * b + c * c);
}

// ---------------------------------------------------------------------------
// Block 2 front half (per atom, one warp each):
//   t[c][j] = sum_o gate[m,o] * vW[c][o] * Wmix2[o][j]   (vW = vmix cols 256:512)
//   vvn2[m] = || t[:,0] || ;  vw2[m,c] = t[c][1]
// ---------------------------------------------------------------------------
__global__ void stage2a_kernel(const float* __restrict__ vmix,
                               const float* __restrict__ gate,
                               const float* __restrict__ Wmix2,
                               float* __restrict__ vvn2,
                               float* __restrict__ vw2, int natoms) {
    __shared__ float sW[512];
    for (int i = threadIdx.x; i < 512; i += blockDim.x) sW[i] = Wmix2[i];
    __syncthreads();
    int warp = threadIdx.x >> 5, lane = threadIdx.x & 31;
    int m = blockIdx.x * 8 + warp;
    if (m >= natoms) return;
    const float* g  = gate + (size_t)m * 256;
    const float* vw = vmix + (size_t)3 * m * 512 + 256;
    float t00 = 0, t01 = 0, t10 = 0, t11 = 0, t20 = 0, t21 = 0;
#pragma unroll
    for (int i = 0; i < 8; i++) {
        int o = lane + 32 * i;
        float ga = g[o];
        float w0 = sW[2 * o], w1 = sW[2 * o + 1];
        float p0 = ga * vw[o];
        float p1 = ga * vw[512 + o];
        float p2 = ga * vw[1024 + o];
        t00 += p0 * w0; t01 += p0 * w1;
        t10 += p1 * w0; t11 += p1 * w1;
        t20 += p2 * w0; t21 += p2 * w1;
    }
#pragma unroll
    for (int off = 16; off; off >>= 1) {
        t00 += __shfl_xor_sync(0xffffffffu, t00, off);
        t01 += __shfl_xor_sync(0xffffffffu, t01, off);
        t10 += __shfl_xor_sync(0xffffffffu, t10, off);
        t11 += __shfl_xor_sync(0xffffffffu, t11, off);
        t20 += __shfl_xor_sync(0xffffffffu, t20, off);
        t21 += __shfl_xor_sync(0xffffffffu, t21, off);
    }
    if (lane == 0) {
        vvn2[m] = sqrtf(t00 * t00 + t10 * t10 + t20 * t20);
        vw2[3 * m + 0] = t01;
        vw2[3 * m + 1] = t11;
        vw2[3 * m + 2] = t21;
    }
}

// ---------------------------------------------------------------------------
// Block 2 back half + outputs (per atom, one warp each):
//   x2 = h2 @ W2b + b2b ; charge = x2[0] (no act) ; gate2 = x2[1]
//   v2[c] = gate2 * vw2[m,c] ; y[c] = v2[c] + pos[m,c]*charge
//   atomicAdd into per-molecule sums (out[0:3M] = y, out[3M:6M] = y_vector)
// ---------------------------------------------------------------------------
__global__ void stage2b_kernel(const float* __restrict__ h2,
                               const float* __restrict__ W2b,
                               const float* __restrict__ b2b,
                               const float* __restrict__ vw2,
                               const float* __restrict__ pos,
                               const int* __restrict__ batch,
                               float* __restrict__ out, int natoms, int nmol) {
    __shared__ float sW[512];
    for (int i = threadIdx.x; i < 512; i += blockDim.x) sW[i] = W2b[i];
    __syncthreads();
    int warp = threadIdx.x >> 5, lane = threadIdx.x & 31;
    int m = blockIdx.x * 8 + warp;
    if (m >= natoms) return;
    const float* h = h2 + (size_t)m * 256;
    float x0 = 0, x1 = 0;
#pragma unroll
    for (int i = 0; i < 8; i++) {
        int k = lane + 32 * i;
        float hv = h[k];
        x0 += hv * sW[2 * k];
        x1 += hv * sW[2 * k + 1];
    }
#pragma unroll
    for (int off = 16; off; off >>= 1) {
        x0 += __shfl_xor_sync(0xffffffffu, x0, off);
        x1 += __shfl_xor_sync(0xffffffffu, x1, off);
    }
    if (lane == 0) {
        float charge = x0 + b2b[0];
        float gate2  = x1 + b2b[1];
        int b = batch[m];
#pragma unroll
        for (int c = 0; c < 3; c++) {
            float v2 = gate2 * vw2[3 * m + c];
            float y  = v2 + pos[3 * m + c] * charge;
            atomicAdd(&out[(size_t)b * 3 + c], y);
            atomicAdd(&out[(size_t)nmol * 3 + (size_t)b * 3 + c], v2);
        }
    }
}

// ---------------------------------------------------------------------------
extern "C" void kernel_launch(void* const* d_in, const int* in_sizes, int n_in,
                              void* d_out, int out_size) {
    const float* pos   = (const float*)d_in[0];
    const float* l0    = (const float*)d_in[1];
    const float* l1    = (const float*)d_in[2];
    const int*   batch = (const int*)d_in[3];
    const float* Wmix1 = (const float*)d_in[4];
    const float* W1a   = (const float*)d_in[5];
    const float* b1a   = (const float*)d_in[6];
    const float* W2a   = (const float*)d_in[7];
    const float* b2a   = (const float*)d_in[8];
    const float* Wmix2 = (const float*)d_in[9];
    const float* W1b   = (const float*)d_in[10];
    const float* b1b   = (const float*)d_in[11];
    const float* W2b   = (const float*)d_in[12];
    const float* b2b   = (const float*)d_in[13];

    const int natoms = in_sizes[3];
    const int nmol   = out_size / 6;
    float* out = (float*)d_out;

    float *vmix, *vvn, *h, *s1, *gate, *vvn2, *vw2;
    cudaGetSymbolAddress((void**)&vmix, g_vmix);
    cudaGetSymbolAddress((void**)&vvn,  g_vvn);
    cudaGetSymbolAddress((void**)&h,    g_h);
    cudaGetSymbolAddress((void**)&s1,   g_s1);
    cudaGetSymbolAddress((void**)&gate, g_gate);
    cudaGetSymbolAddress((void**)&vvn2, g_vvn2);
    cudaGetSymbolAddress((void**)&vw2,  g_vw2);

    cudaMemsetAsync(d_out, 0, (size_t)out_size * sizeof(float));

    const int mBlocks3 = (3 * natoms + 127) / 128;
    const int mBlocks  = (natoms + 127) / 128;

    // GEMM1: vmix = l1 @ Wmix1      (3N x 256) @ (256 x 512)
    {
        GP p;
        p.A0 = l1; p.A1 = nullptr; p.ksplit = 256;
        p.B = Wmix1; p.M = 3 * natoms; p.N = 512; p.K = 256;
        p.C0 = vmix; p.C1 = nullptr; p.bias = nullptr; p.u = nullptr; p.vrow = nullptr;
        gemm_k<0><<<dim3(4, mBlocks3), 256>>>(p);
    }

    // vVn from vmix columns 0:256
    vvn_kernel<<<natoms, 256>>>(vmix, vvn, natoms);

    // GEMM2: h = silu([l0 | vVn] @ W1a + b1a)   (N x 512) @ (512 x 256)
    {
        GP p;
        p.A0 = l0; p.A1 = vvn; p.ksplit = 256;
        p.B = W1a; p.M = natoms; p.N = 256; p.K = 512;
        p.C0 = h; p.C1 = nullptr; p.bias = b1a; p.u = nullptr; p.vrow = nullptr;
        gemm_k<1><<<dim3(2, mBlocks), 256>>>(p);
    }

    // GEMM3: x = h @ W2a + b2a ; s1 = silu(x[:, :256]) ; gate = x[:, 256:]
    {
        GP p;
        p.A0 = h; p.A1 = nullptr; p.ksplit = 256;
        p.B = W2a; p.M = natoms; p.N = 512; p.K = 256;
        p.C0 = s1; p.C1 = gate; p.bias = b2a; p.u = nullptr; p.vrow = nullptr;
        gemm_k<2><<<dim3(4, mBlocks), 256>>>(p);
    }

    // Block 2 front: vmix2 contraction, vvn2, vw2
    stage2a_kernel<<<(natoms + 7) / 8, 256>>>(vmix, gate, Wmix2, vvn2, vw2, natoms);

    // GEMM4: h2 = silu(s1 @ W1b[0:256] + vvn2*W1b[256] + b1b)  (reuse g_h)
    {
        GP p;
        p.A0 = s1; p.A1 = nullptr; p.ksplit = 256;
        p.B = W1b; p.M = natoms; p.N = 256; p.K = 256;
        p.C0 = h; p.C1 = nullptr; p.bias = b1b; p.u = vvn2; p.vrow = W1b + 256 * 256;
        gemm_k<3><<<dim3(2, mBlocks), 256>>>(p);
    }

    // Block 2 back: x2 = h2 @ W2b + b2b, gating, segment sums
    stage2b_kernel<<<(natoms + 7) / 8, 256>>>(h, W2b, b2b, vw2, pos, batch,
                                              out, natoms, nmol);
}

// round 3
// speedup vs baseline: 2.1350x; 2.1350x over previous
#include <cuda_runtime.h>
#include <cuda_bf16.h>
#include <cstdint>
#include <cstddef>

// ---------------------------------------------------------------------------
// Dipole head: split-bf16 (hi/lo) 3-pass GEMMs on mma.sync (HMMA), fp32 accum.
// tcgen05 is unavailable (harness PTX target is compute_103, not 103a), so we
// drive the tensor cores through baseline mma.sync.m16n8k16.bf16.
// ---------------------------------------------------------------------------

#define NA_MAX 200000
#define MPAD1  600128   // padded rows for GEMM1 (3*N atoms)
#define MPAD   200128   // padded rows for per-atom GEMMs

// ---------------- global scratch (zero-initialized at module load) ----------
__device__ __align__(128) float g_vmix[(size_t)3 * NA_MAX * 512];
__device__ __align__(128) __nv_bfloat16 g_a1h[(size_t)MPAD1 * 256];
__device__ __align__(128) __nv_bfloat16 g_a1l[(size_t)MPAD1 * 256];
__device__ __align__(128) __nv_bfloat16 g_a2h[(size_t)MPAD * 512];
__device__ __align__(128) __nv_bfloat16 g_a2l[(size_t)MPAD * 512];
__device__ __align__(128) __nv_bfloat16 g_a3h[(size_t)MPAD * 256];
__device__ __align__(128) __nv_bfloat16 g_a3l[(size_t)MPAD * 256];
__device__ __align__(128) __nv_bfloat16 g_a4h[(size_t)MPAD * 256];
__device__ __align__(128) __nv_bfloat16 g_a4l[(size_t)MPAD * 256];
__device__ __align__(128) float g_gate[(size_t)NA_MAX * 256];
__device__ __align__(128) float g_h2[(size_t)NA_MAX * 256];
__device__ float g_vvn2[NA_MAX];
__device__ float g_vw2[3 * NA_MAX];
__device__ __align__(128) __nv_bfloat16 g_bt1h[512 * 256], g_bt1l[512 * 256];
__device__ __align__(128) __nv_bfloat16 g_bt2h[256 * 512], g_bt2l[256 * 512];
__device__ __align__(128) __nv_bfloat16 g_bt3h[512 * 256], g_bt3l[512 * 256];
__device__ __align__(128) __nv_bfloat16 g_bt4h[256 * 256], g_bt4l[256 * 256];

// ---------------- helpers ----------------------------------------------
__device__ __forceinline__ uint32_t smem_u32(const void* p) {
    uint32_t a;
    asm("{ .reg .u64 t; cvta.to.shared.u64 t, %1; cvt.u32.u64 %0, t; }"
        : "=r"(a) : "l"(p));
    return a;
}
#define SWZ128(off) ((off) ^ (((off) >> 3) & 0x70))

__device__ __forceinline__ void cp16(uint32_t saddr, const void* gaddr) {
    asm volatile("cp.async.cg.shared.global [%0], [%1], 16;\n"
                 :: "r"(saddr), "l"(gaddr));
}
__device__ __forceinline__ void cp_commit() {
    asm volatile("cp.async.commit_group;\n" ::: "memory");
}

__device__ __forceinline__ void ldsm_x4(uint32_t* r, uint32_t a) {
    asm volatile("ldmatrix.sync.aligned.m8n8.x4.shared.b16 {%0,%1,%2,%3}, [%4];"
                 : "=r"(r[0]), "=r"(r[1]), "=r"(r[2]), "=r"(r[3]) : "r"(a));
}

__device__ __forceinline__ void mma16816(float* d, const uint32_t* a,
                                         const uint32_t* b) {
    asm volatile(
        "mma.sync.aligned.m16n8k16.row.col.f32.bf16.bf16.f32 "
        "{%0,%1,%2,%3}, {%4,%5,%6,%7}, {%8,%9}, {%0,%1,%2,%3};\n"
        : "+f"(d[0]), "+f"(d[1]), "+f"(d[2]), "+f"(d[3])
        : "r"(a[0]), "r"(a[1]), "r"(a[2]), "r"(a[3]), "r"(b[0]), "r"(b[1]));
}

__device__ __forceinline__ float silu_f(float x) { return x / (1.0f + __expf(-x)); }

__device__ __forceinline__ void split_bf16(float v, __nv_bfloat16& h, __nv_bfloat16& l) {
    h = __float2bfloat16_rn(v);
    l = __float2bfloat16_rn(v - __bfloat162float(h));
}

// ---------------------------------------------------------------------------
// HMMA GEMM: D[128x128 tile] = (Ah+Al) @ (Bh+Bl)^T  (3-pass split-bf16)
//   A: [Mpad, K] bf16 row-major.  B: [N, K] bf16 (pre-transposed weights).
//   K-chunk 64, 3-stage cp.async pipeline, 256 threads (8 warps, 2m x 4n).
// EPI 0: fp32 -> C0 (ldc=512)
// EPI 1: silu(v+bias) -> bf16 hi/lo (ld 256)
// EPI 2: n<256: silu(v+bias)->hi/lo ; n>=256: v+bias -> C0 fp32 (ld 256)
// EPI 3: silu(v + u[m]*vrow[n] + bias) -> C0 fp32 (ld 256)
// ---------------------------------------------------------------------------
struct MP {
    const __nv_bfloat16 *Ah, *Al;
    const __nv_bfloat16 *Bh, *Bl;
    int M;        // real rows (epilogue guard)
    int K;        // multiple of 64
    float *C0;
    __nv_bfloat16 *Oh, *Ol;
    const float *bias, *u, *vrow;
};

#define STG_SZ 65536   // per stage: Ah 16K | Al 16K | Bh 16K | Bl 16K
#define SMEM_DYN (3 * STG_SZ)

template <int EPI>
__global__ void __launch_bounds__(256, 1) gemm_mma(const MP p) {
    extern __shared__ __align__(1024) char smem[];
    const uint32_t sb = smem_u32(smem);
    const int tid  = threadIdx.x;
    const int wid  = tid >> 5;
    const int lane = tid & 31;
    const int wm   = wid >> 2;   // 0..1  (64-row slab)
    const int wn   = wid & 3;    // 0..3  (32-col slab)
    const int row0 = blockIdx.y * 128;
    const int col0 = blockIdx.x * 128;

    // ldmatrix per-lane address components (swizzle XOR depends only on row).
    const int      rA0 = wm * 64 + (lane & 7) + ((lane >> 3) & 1) * 8;
    const uint32_t xA  = (uint32_t)(rA0 & 7) << 4;
    const uint32_t kA  = (uint32_t)(lane >> 4) * 16;
    const int      rB0 = wn * 32 + ((lane >> 4) * 8) + (lane & 7);
    const uint32_t xB  = (uint32_t)(rB0 & 7) << 4;
    const uint32_t kB  = (uint32_t)((lane >> 3) & 1) * 16;

    float acc[4][4][4];
#pragma unroll
    for (int i = 0; i < 4; i++)
#pragma unroll
        for (int j = 0; j < 4; j++)
#pragma unroll
            for (int q = 0; q < 4; q++) acc[i][j][q] = 0.f;

    const int NC = p.K >> 6;   // 64-wide K chunks

    auto load_chunk = [&](int kc, int s) {
        const uint32_t base = sb + s * STG_SZ;
        const int koff = kc * 64;
#pragma unroll
        for (int i = 0; i < 4; i++) {
            int idx = i * 256 + tid;
            int r = idx >> 3, ch = idx & 7;
            uint32_t so = SWZ128((uint32_t)(r * 128 + ch * 16));
            size_t ga = (size_t)(row0 + r) * p.K + koff + ch * 8;
            size_t gb = (size_t)(col0 + r) * p.K + koff + ch * 8;
            cp16(base + so,         p.Ah + ga);
            cp16(base + 16384 + so, p.Al + ga);
            cp16(base + 32768 + so, p.Bh + gb);
            cp16(base + 49152 + so, p.Bl + gb);
        }
        cp_commit();
    };

    load_chunk(0, 0);
    if (NC > 1) load_chunk(1, 1);

    for (int c = 0; c < NC; c++) {
        const int s = c % 3;
        if (c + 1 < NC) asm volatile("cp.async.wait_group 1;\n" ::: "memory");
        else            asm volatile("cp.async.wait_group 0;\n" ::: "memory");
        __syncthreads();

        const uint32_t base = sb + s * STG_SZ;
#pragma unroll
        for (int ks = 0; ks < 4; ks++) {
            const uint32_t kbA = ((uint32_t)(ks * 32) + kA) ^ xA;
            const uint32_t kbB = ((uint32_t)(ks * 32) + kB) ^ xB;
            uint32_t Ah[4][4], Al[4][4], Bh[4][2], Bl[4][2];
#pragma unroll
            for (int i = 0; i < 4; i++) {
                uint32_t ro = (uint32_t)(rA0 + i * 16) * 128;
                ldsm_x4(Ah[i], base + ro + kbA);
                ldsm_x4(Al[i], base + 16384 + ro + kbA);
            }
#pragma unroll
            for (int jp = 0; jp < 2; jp++) {
                uint32_t ro = (uint32_t)(rB0 + jp * 16) * 128;
                uint32_t r4[4];
                ldsm_x4(r4, base + 32768 + ro + kbB);
                Bh[2 * jp][0] = r4[0]; Bh[2 * jp][1] = r4[1];
                Bh[2 * jp + 1][0] = r4[2]; Bh[2 * jp + 1][1] = r4[3];
                ldsm_x4(r4, base + 49152 + ro + kbB);
                Bl[2 * jp][0] = r4[0]; Bl[2 * jp][1] = r4[1];
                Bl[2 * jp + 1][0] = r4[2]; Bl[2 * jp + 1][1] = r4[3];
            }
#pragma unroll
            for (int i = 0; i < 4; i++)
#pragma unroll
                for (int j = 0; j < 4; j++) mma16816(acc[i][j], Ah[i], Bh[j]);
#pragma unroll
            for (int i = 0; i < 4; i++)
#pragma unroll
                for (int j = 0; j < 4; j++) mma16816(acc[i][j], Ah[i], Bl[j]);
#pragma unroll
            for (int i = 0; i < 4; i++)
#pragma unroll
                for (int j = 0; j < 4; j++) mma16816(acc[i][j], Al[i], Bh[j]);
        }
        __syncthreads();
        if (c + 2 < NC) load_chunk(c + 2, (c + 2) % 3);
    }

    // ---------------- epilogue ----------------
    const int mrow = lane >> 2;          // 0..7
    const int ncol = (lane & 3) * 2;     // 0,2,4,6

#pragma unroll
    for (int i = 0; i < 4; i++) {
        const int mbase = row0 + wm * 64 + i * 16 + mrow;
#pragma unroll
        for (int half = 0; half < 2; half++) {
            const int m = mbase + half * 8;
            if (m >= p.M) continue;
#pragma unroll
            for (int j = 0; j < 4; j++) {
                const int n = col0 + wn * 32 + j * 8 + ncol;
                float v0 = acc[i][j][half * 2 + 0];
                float v1 = acc[i][j][half * 2 + 1];
                if (EPI == 0) {
                    *(float2*)(p.C0 + (size_t)m * 512 + n) = make_float2(v0, v1);
                } else if (EPI == 1) {
                    v0 = silu_f(v0 + p.bias[n]);
                    v1 = silu_f(v1 + p.bias[n + 1]);
                    __nv_bfloat16 h0, l0, h1, l1;
                    split_bf16(v0, h0, l0);
                    split_bf16(v1, h1, l1);
                    *(__nv_bfloat162*)(p.Oh + (size_t)m * 256 + n) = __nv_bfloat162(h0, h1);
                    *(__nv_bfloat162*)(p.Ol + (size_t)m * 256 + n) = __nv_bfloat162(l0, l1);
                } else if (EPI == 2) {
                    v0 += p.bias[n];
                    v1 += p.bias[n + 1];
                    if (n < 256) {
                        v0 = silu_f(v0);
                        v1 = silu_f(v1);
                        __nv_bfloat16 h0, l0, h1, l1;
                        split_bf16(v0, h0, l0);
                        split_bf16(v1, h1, l1);
                        *(__nv_bfloat162*)(p.Oh + (size_t)m * 256 + n) = __nv_bfloat162(h0, h1);
                        *(__nv_bfloat162*)(p.Ol + (size_t)m * 256 + n) = __nv_bfloat162(l0, l1);
                    } else {
                        *(float2*)(p.C0 + (size_t)m * 256 + (n - 256)) = make_float2(v0, v1);
                    }
                } else {  // EPI 3
                    float um = p.u[m];
                    v0 = silu_f(v0 + um * p.vrow[n]     + p.bias[n]);
                    v1 = silu_f(v1 + um * p.vrow[n + 1] + p.bias[n + 1]);
                    *(float2*)(p.C0 + (size_t)m * 256 + n) = make_float2(v0, v1);
                }
            }
        }
    }
}

// ---------------------------------------------------------------------------
// conversions
// ---------------------------------------------------------------------------
__global__ void wt_conv(const float* __restrict__ W,
                        __nv_bfloat16* __restrict__ th,
                        __nv_bfloat16* __restrict__ tl, int K, int N) {
    int idx = blockIdx.x * blockDim.x + threadIdx.x;
    if (idx >= K * N) return;
    int k = idx / N, n = idx % N;
    __nv_bfloat16 h, l;
    split_bf16(W[idx], h, l);
    th[(size_t)n * K + k] = h;
    tl[(size_t)n * K + k] = l;
}

__global__ void act_conv(const float* __restrict__ src,
                         __nv_bfloat16* __restrict__ dh,
                         __nv_bfloat16* __restrict__ dl,
                         int M, int Ks, int ldd, int coff) {
    int idx = blockIdx.x * blockDim.x + threadIdx.x;
    if (idx >= M * Ks) return;
    int m = idx / Ks, c = idx - m * Ks;
    __nv_bfloat16 h, l;
    split_bf16(src[idx], h, l);
    dh[(size_t)m * ldd + coff + c] = h;
    dl[(size_t)m * ldd + coff + c] = l;
}

__global__ void vvn_conv(const float* __restrict__ vmix,
                         __nv_bfloat16* __restrict__ dh,
                         __nv_bfloat16* __restrict__ dl, int natoms) {
    int m = blockIdx.x, o = threadIdx.x;
    if (m >= natoms) return;
    const float* r = vmix + (size_t)3 * m * 512 + o;
    float a = r[0], b = r[512], c = r[1024];
    float v = sqrtf(a * a + b * b + c * c);
    __nv_bfloat16 h, l;
    split_bf16(v, h, l);
    dh[(size_t)m * 512 + 256 + o] = h;
    dl[(size_t)m * 512 + 256 + o] = l;
}

// ---------------------------------------------------------------------------
// Block-2 glue
// ---------------------------------------------------------------------------
__global__ void stage2a_kernel(const float* __restrict__ vmix,
                               const float* __restrict__ gate,
                               const float* __restrict__ Wmix2,
                               float* __restrict__ vvn2,
                               float* __restrict__ vw2, int natoms) {
    __shared__ float sW[512];
    for (int i = threadIdx.x; i < 512; i += blockDim.x) sW[i] = Wmix2[i];
    __syncthreads();
    int warp = threadIdx.x >> 5, lane = threadIdx.x & 31;
    int m = blockIdx.x * 8 + warp;
    if (m >= natoms) return;
    const float* g  = gate + (size_t)m * 256;
    const float* vw = vmix + (size_t)3 * m * 512 + 256;
    float t00 = 0, t01 = 0, t10 = 0, t11 = 0, t20 = 0, t21 = 0;
#pragma unroll
    for (int i = 0; i < 8; i++) {
        int o = lane + 32 * i;
        float ga = g[o];
        float w0 = sW[2 * o], w1 = sW[2 * o + 1];
        float p0 = ga * vw[o];
        float p1 = ga * vw[512 + o];
        float p2 = ga * vw[1024 + o];
        t00 += p0 * w0; t01 += p0 * w1;
        t10 += p1 * w0; t11 += p1 * w1;
        t20 += p2 * w0; t21 += p2 * w1;
    }
#pragma unroll
    for (int off = 16; off; off >>= 1) {
        t00 += __shfl_xor_sync(0xffffffffu, t00, off);
        t01 += __shfl_xor_sync(0xffffffffu, t01, off);
        t10 += __shfl_xor_sync(0xffffffffu, t10, off);
        t11 += __shfl_xor_sync(0xffffffffu, t11, off);
        t20 += __shfl_xor_sync(0xffffffffu, t20, off);
        t21 += __shfl_xor_sync(0xffffffffu, t21, off);
    }
    if (lane == 0) {
        vvn2[m] = sqrtf(t00 * t00 + t10 * t10 + t20 * t20);
        vw2[3 * m + 0] = t01;
        vw2[3 * m + 1] = t11;
        vw2[3 * m + 2] = t21;
    }
}

__global__ void stage2b_kernel(const float* __restrict__ h2,
                               const float* __restrict__ W2b,
                               const float* __restrict__ b2b,
                               const float* __restrict__ vw2,
                               const float* __restrict__ pos,
                               const int* __restrict__ batch,
                               float* __restrict__ out, int natoms, int nmol) {
    __shared__ float sW[512];
    for (int i = threadIdx.x; i < 512; i += blockDim.x) sW[i] = W2b[i];
    __syncthreads();
    int warp = threadIdx.x >> 5, lane = threadIdx.x & 31;
    int m = blockIdx.x * 8 + warp;
    if (m >= natoms) return;
    const float* h = h2 + (size_t)m * 256;
    float x0 = 0, x1 = 0;
#pragma unroll
    for (int i = 0; i < 8; i++) {
        int k = lane + 32 * i;
        float hv = h[k];
        x0 += hv * sW[2 * k];
        x1 += hv * sW[2 * k + 1];
    }
#pragma unroll
    for (int off = 16; off; off >>= 1) {
        x0 += __shfl_xor_sync(0xffffffffu, x0, off);
        x1 += __shfl_xor_sync(0xffffffffu, x1, off);
    }
    if (lane == 0) {
        float charge = x0 + b2b[0];
        float gate2  = x1 + b2b[1];
        int b = batch[m];
#pragma unroll
        for (int c = 0; c < 3; c++) {
            float v2 = gate2 * vw2[3 * m + c];
            float y  = v2 + pos[3 * m + c] * charge;
            atomicAdd(&out[(size_t)b * 3 + c], y);
            atomicAdd(&out[(size_t)nmol * 3 + (size_t)b * 3 + c], v2);
        }
    }
}

// ---------------------------------------------------------------------------
extern "C" void kernel_launch(void* const* d_in, const int* in_sizes, int n_in,
                              void* d_out, int out_size) {
    const float* pos   = (const float*)d_in[0];
    const float* l0    = (const float*)d_in[1];
    const float* l1    = (const float*)d_in[2];
    const int*   batch = (const int*)d_in[3];
    const float* Wmix1 = (const float*)d_in[4];
    const float* W1a   = (const float*)d_in[5];
    const float* b1a   = (const float*)d_in[6];
    const float* W2a   = (const float*)d_in[7];
    const float* b2a   = (const float*)d_in[8];
    const float* Wmix2 = (const float*)d_in[9];
    const float* W1b   = (const float*)d_in[10];
    const float* b1b   = (const float*)d_in[11];
    const float* W2b   = (const float*)d_in[12];
    const float* b2b   = (const float*)d_in[13];

    const int natoms = in_sizes[3];
    const int nmol   = out_size / 6;
    float* out = (float*)d_out;

    float *vmix, *gate, *h2, *vvn2, *vw2;
    __nv_bfloat16 *a1h, *a1l, *a2h, *a2l, *a3h, *a3l, *a4h, *a4l;
    __nv_bfloat16 *bt1h, *bt1l, *bt2h, *bt2l, *bt3h, *bt3l, *bt4h, *bt4l;
    cudaGetSymbolAddress((void**)&vmix, g_vmix);
    cudaGetSymbolAddress((void**)&gate, g_gate);
    cudaGetSymbolAddress((void**)&h2,   g_h2);
    cudaGetSymbolAddress((void**)&vvn2, g_vvn2);
    cudaGetSymbolAddress((void**)&vw2,  g_vw2);
    cudaGetSymbolAddress((void**)&a1h, g_a1h);  cudaGetSymbolAddress((void**)&a1l, g_a1l);
    cudaGetSymbolAddress((void**)&a2h, g_a2h);  cudaGetSymbolAddress((void**)&a2l, g_a2l);
    cudaGetSymbolAddress((void**)&a3h, g_a3h);  cudaGetSymbolAddress((void**)&a3l, g_a3l);
    cudaGetSymbolAddress((void**)&a4h, g_a4h);  cudaGetSymbolAddress((void**)&a4l, g_a4l);
    cudaGetSymbolAddress((void**)&bt1h, g_bt1h); cudaGetSymbolAddress((void**)&bt1l, g_bt1l);
    cudaGetSymbolAddress((void**)&bt2h, g_bt2h); cudaGetSymbolAddress((void**)&bt2l, g_bt2l);
    cudaGetSymbolAddress((void**)&bt3h, g_bt3h); cudaGetSymbolAddress((void**)&bt3l, g_bt3l);
    cudaGetSymbolAddress((void**)&bt4h, g_bt4h); cudaGetSymbolAddress((void**)&bt4l, g_bt4l);

    cudaFuncSetAttribute(gemm_mma<0>, cudaFuncAttributeMaxDynamicSharedMemorySize, SMEM_DYN);
    cudaFuncSetAttribute(gemm_mma<1>, cudaFuncAttributeMaxDynamicSharedMemorySize, SMEM_DYN);
    cudaFuncSetAttribute(gemm_mma<2>, cudaFuncAttributeMaxDynamicSharedMemorySize, SMEM_DYN);
    cudaFuncSetAttribute(gemm_mma<3>, cudaFuncAttributeMaxDynamicSharedMemorySize, SMEM_DYN);

    cudaMemsetAsync(d_out, 0, (size_t)out_size * sizeof(float));

    const int M1  = 3 * natoms;
    const int mt1 = (M1 + 127) / 128;
    const int mt  = (natoms + 127) / 128;

    // weight transposes + splits
    wt_conv<<<(256 * 512 + 255) / 256, 256>>>(Wmix1, bt1h, bt1l, 256, 512);
    wt_conv<<<(512 * 256 + 255) / 256, 256>>>(W1a,   bt2h, bt2l, 512, 256);
    wt_conv<<<(256 * 512 + 255) / 256, 256>>>(W2a,   bt3h, bt3l, 256, 512);
    wt_conv<<<(256 * 256 + 255) / 256, 256>>>(W1b,   bt4h, bt4l, 256, 256);

    // activation splits
    act_conv<<<(int)(((size_t)M1 * 256 + 255) / 256), 256>>>(l1, a1h, a1l, M1, 256, 256, 0);
    act_conv<<<(int)(((size_t)natoms * 256 + 255) / 256), 256>>>(l0, a2h, a2l, natoms, 256, 512, 0);

    // GEMM1: vmix = l1 @ Wmix1  (3N x 512)
    {
        MP p = {};
        p.Ah = a1h; p.Al = a1l; p.Bh = bt1h; p.Bl = bt1l;
        p.M = M1; p.K = 256; p.C0 = vmix;
        gemm_mma<0><<<dim3(4, mt1), 256, SMEM_DYN>>>(p);
    }

    // vVn -> A2 cols 256:512
    vvn_conv<<<natoms, 256>>>(vmix, a2h, a2l, natoms);

    // GEMM2: h = silu([l0|vVn] @ W1a + b1a) -> a3 (hi/lo)
    {
        MP p = {};
        p.Ah = a2h; p.Al = a2l; p.Bh = bt2h; p.Bl = bt2l;
        p.M = natoms; p.K = 512; p.Oh = a3h; p.Ol = a3l; p.bias = b1a;
        gemm_mma<1><<<dim3(2, mt), 256, SMEM_DYN>>>(p);
    }

    // GEMM3: x = h @ W2a + b2a ; s1=silu(x[:,:256])->a4 ; gate=x[:,256:]
    {
        MP p = {};
        p.Ah = a3h; p.Al = a3l; p.Bh = bt3h; p.Bl = bt3l;
        p.M = natoms; p.K = 256; p.Oh = a4h; p.Ol = a4l; p.C0 = gate; p.bias = b2a;
        gemm_mma<2><<<dim3(4, mt), 256, SMEM_DYN>>>(p);
    }

    // block-2 front: vvn2, vw2
    stage2a_kernel<<<(natoms + 7) / 8, 256>>>(vmix, gate, Wmix2, vvn2, vw2, natoms);

    // GEMM4: h2 = silu(s1 @ W1b[:256] + vvn2*W1b[256] + b1b)
    {
        MP p = {};
        p.Ah = a4h; p.Al = a4l; p.Bh = bt4h; p.Bl = bt4l;
        p.M = natoms; p.K = 256; p.C0 = h2; p.bias = b1b;
        p.u = vvn2; p.vrow = W1b + 256 * 256;
        gemm_mma<3><<<dim3(2, mt), 256, SMEM_DYN>>>(p);
    }

    // block-2 back + segment sums
    stage2b_kernel<<<(natoms + 7) / 8, 256>>>(h2, W2b, b2b, vw2, pos, batch,
                                              out, natoms, nmol);
}

// round 4
// speedup vs baseline: 2.5341x; 1.1869x over previous
#include <cuda_runtime.h>
#include <cuda_bf16.h>
#include <cstdint>
#include <cstddef>

// ---------------------------------------------------------------------------
// Dipole head: split-bf16 (hi/lo) 3-pass GEMMs on mma.sync (HMMA), fp32 accum.
// R4: 128x256 CTA tiles (2-stage cp.async), GEMM1-fused vector norms,
//     vectorized conversions.
// ---------------------------------------------------------------------------

#define NA_MAX 200000
#define MPAD1  600128   // padded rows for GEMM1 (3*N atoms)
#define MPAD   200128   // padded rows for per-atom GEMMs

// ---------------- global scratch (zero-initialized at module load) ----------
__device__ __align__(128) float g_vw[(size_t)3 * NA_MAX * 256];   // vW fp32
__device__ __align__(128) __nv_bfloat16 g_a1h[(size_t)MPAD1 * 256];
__device__ __align__(128) __nv_bfloat16 g_a1l[(size_t)MPAD1 * 256];
__device__ __align__(128) __nv_bfloat16 g_a2h[(size_t)MPAD * 512];
__device__ __align__(128) __nv_bfloat16 g_a2l[(size_t)MPAD * 512];
__device__ __align__(128) __nv_bfloat16 g_a3h[(size_t)MPAD * 256];
__device__ __align__(128) __nv_bfloat16 g_a3l[(size_t)MPAD * 256];
__device__ __align__(128) __nv_bfloat16 g_a4h[(size_t)MPAD * 256];
__device__ __align__(128) __nv_bfloat16 g_a4l[(size_t)MPAD * 256];
__device__ __align__(128) float g_gate[(size_t)NA_MAX * 256];
__device__ __align__(128) float g_h2[(size_t)NA_MAX * 256];
__device__ float g_vvn2[NA_MAX];
__device__ float g_vw2[3 * NA_MAX];
__device__ __align__(128) __nv_bfloat16 g_bt1h[512 * 256], g_bt1l[512 * 256];
__device__ __align__(128) __nv_bfloat16 g_bt2h[256 * 512], g_bt2l[256 * 512];
__device__ __align__(128) __nv_bfloat16 g_bt3h[512 * 256], g_bt3l[512 * 256];
__device__ __align__(128) __nv_bfloat16 g_bt4h[256 * 256], g_bt4l[256 * 256];

// ---------------- helpers ----------------------------------------------
__device__ __forceinline__ uint32_t smem_u32(const void* p) {
    uint32_t a;
    asm("{ .reg .u64 t; cvta.to.shared.u64 t, %1; cvt.u32.u64 %0, t; }"
        : "=r"(a) : "l"(p));
    return a;
}
#define SWZ128(off) ((off) ^ (((off) >> 3) & 0x70))

__device__ __forceinline__ void cp16(uint32_t saddr, const void* gaddr) {
    asm volatile("cp.async.cg.shared.global [%0], [%1], 16;\n"
                 :: "r"(saddr), "l"(gaddr));
}
__device__ __forceinline__ void cp_commit() {
    asm volatile("cp.async.commit_group;\n" ::: "memory");
}

__device__ __forceinline__ void ldsm_x4(uint32_t* r, uint32_t a) {
    asm volatile("ldmatrix.sync.aligned.m8n8.x4.shared.b16 {%0,%1,%2,%3}, [%4];"
                 : "=r"(r[0]), "=r"(r[1]), "=r"(r[2]), "=r"(r[3]) : "r"(a));
}

__device__ __forceinline__ void mma16816(float* d, const uint32_t* a,
                                         const uint32_t* b) {
    asm volatile(
        "mma.sync.aligned.m16n8k16.row.col.f32.bf16.bf16.f32 "
        "{%0,%1,%2,%3}, {%4,%5,%6,%7}, {%8,%9}, {%0,%1,%2,%3};\n"
        : "+f"(d[0]), "+f"(d[1]), "+f"(d[2]), "+f"(d[3])
        : "r"(a[0]), "r"(a[1]), "r"(a[2]), "r"(a[3]), "r"(b[0]), "r"(b[1]));
}

__device__ __forceinline__ float silu_f(float x) { return x / (1.0f + __expf(-x)); }

__device__ __forceinline__ void split_bf16(float v, __nv_bfloat16& h, __nv_bfloat16& l) {
    h = __float2bfloat16_rn(v);
    l = __float2bfloat16_rn(v - __bfloat162float(h));
}

// ---------------------------------------------------------------------------
// HMMA GEMM, CTA tile 128x256, warp tile 64x64 (8 warps), K-chunk 64,
// 2-stage cp.async ring. 3-pass split-bf16 fp32 accumulate.
// EPI 0: GEMM1 special — col0==0: vector norms -> Oh/Ol cols 256:512;
//        col0==256: vW fp32 -> C0 (ld 256)
// EPI 1: silu(v+bias) -> bf16 hi/lo (ld 256)
// EPI 2: n<256: silu(v+bias)->hi/lo ; n>=256: v+bias -> C0 fp32 (ld 256)
// EPI 3: silu(v + u[m]*vrow[n] + bias) -> C0 fp32 (ld 256)
// ---------------------------------------------------------------------------
struct MP {
    const __nv_bfloat16 *Ah, *Al;
    const __nv_bfloat16 *Bh, *Bl;
    int M;        // real rows (epilogue guard)
    int K;        // multiple of 64
    int mstep;    // row tile stride (128, or 126 for GEMM1)
    float *C0;
    __nv_bfloat16 *Oh, *Ol;
    const float *bias, *u, *vrow;
};

#define OFF_AL 16384
#define OFF_BH 32768
#define OFF_BL 65536
#define STG    98304
#define SMEM_DYN (2 * STG)
#define SROW 264   // fp32 smem tile row stride (epilogue norm path)

template <int EPI>
__global__ void __launch_bounds__(256, 1) gemm_mma(const MP p) {
    extern __shared__ __align__(1024) char smem[];
    const uint32_t sb = smem_u32(smem);
    const int tid  = threadIdx.x;
    const int wid  = tid >> 5;
    const int lane = tid & 31;
    const int wm   = wid >> 2;   // 0..1  (64-row slab)
    const int wn   = wid & 3;    // 0..3  (64-col slab)
    const int row0 = blockIdx.y * p.mstep;
    const int col0 = blockIdx.x * 256;

    // ldmatrix per-lane address components
    const int      rA0 = wm * 64 + (lane & 7) + ((lane >> 3) & 1) * 8;
    const uint32_t xA  = (uint32_t)(rA0 & 7) << 4;
    const uint32_t kA  = (uint32_t)(lane >> 4) * 16;
    const int      rB0 = wn * 64 + ((lane >> 4) * 8) + (lane & 7);
    const uint32_t xB  = (uint32_t)(rB0 & 7) << 4;
    const uint32_t kB  = (uint32_t)((lane >> 3) & 1) * 16;

    float acc[4][8][4];
#pragma unroll
    for (int i = 0; i < 4; i++)
#pragma unroll
        for (int j = 0; j < 8; j++)
#pragma unroll
            for (int q = 0; q < 4; q++) acc[i][j][q] = 0.f;

    const int NC = p.K >> 6;   // 64-wide K chunks

    auto load_chunk = [&](int kc, int s) {
        const uint32_t base = sb + s * STG;
        const int koff = kc * 64;
#pragma unroll
        for (int i = 0; i < 4; i++) {          // A: 128 rows x 128B
            int idx = i * 256 + tid;
            int r = idx >> 3, ch = idx & 7;
            uint32_t so = SWZ128((uint32_t)(r * 128 + ch * 16));
            size_t ga = (size_t)(row0 + r) * p.K + koff + ch * 8;
            cp16(base + so,          p.Ah + ga);
            cp16(base + OFF_AL + so, p.Al + ga);
        }
#pragma unroll
        for (int i = 0; i < 8; i++) {          // B: 256 rows x 128B
            int idx = i * 256 + tid;
            int r = idx >> 3, ch = idx & 7;
            uint32_t so = SWZ128((uint32_t)(r * 128 + ch * 16));
            size_t gb = (size_t)(col0 + r) * p.K + koff + ch * 8;
            cp16(base + OFF_BH + so, p.Bh + gb);
            cp16(base + OFF_BL + so, p.Bl + gb);
        }
        cp_commit();
    };

    load_chunk(0, 0);
    if (NC > 1) load_chunk(1, 1);

    for (int c = 0; c < NC; c++) {
        const int s = c & 1;
        if (c + 1 < NC) asm volatile("cp.async.wait_group 1;\n" ::: "memory");
        else            asm volatile("cp.async.wait_group 0;\n" ::: "memory");
        __syncthreads();

        const uint32_t base = sb + s * STG;
#pragma unroll
        for (int ks = 0; ks < 4; ks++) {
            const uint32_t kbA = ((uint32_t)(ks * 32) + kA) ^ xA;
            const uint32_t kbB = ((uint32_t)(ks * 32) + kB) ^ xB;
            uint32_t Ah4[4][4], Al4[4][4];
#pragma unroll
            for (int i = 0; i < 4; i++) {
                uint32_t ro = (uint32_t)(rA0 + i * 16) * 128;
                ldsm_x4(Ah4[i], base + ro + kbA);
                ldsm_x4(Al4[i], base + OFF_AL + ro + kbA);
            }
#pragma unroll
            for (int jp = 0; jp < 4; jp++) {
                uint32_t ro = (uint32_t)(rB0 + jp * 16) * 128;
                uint32_t bh[4], bl[4];
                ldsm_x4(bh, base + OFF_BH + ro + kbB);
                ldsm_x4(bl, base + OFF_BL + ro + kbB);
#pragma unroll
                for (int i = 0; i < 4; i++) {
                    mma16816(acc[i][2 * jp],     Ah4[i], bh);
                    mma16816(acc[i][2 * jp + 1], Ah4[i], bh + 2);
                    mma16816(acc[i][2 * jp],     Ah4[i], bl);
                    mma16816(acc[i][2 * jp + 1], Ah4[i], bl + 2);
                    mma16816(acc[i][2 * jp],     Al4[i], bh);
                    mma16816(acc[i][2 * jp + 1], Al4[i], bh + 2);
                }
            }
        }
        __syncthreads();
        if (c + 2 < NC) load_chunk(c + 2, s);
    }

    // ---------------- epilogue ----------------
    const int mrow = lane >> 2;          // 0..7
    const int ncol = (lane & 3) * 2;     // 0,2,4,6

    if (EPI == 0 && col0 == 0) {
        // vV tile: stage fp32 accumulators to smem, then compute norms.
        float* st = (float*)smem;
#pragma unroll
        for (int i = 0; i < 4; i++) {
#pragma unroll
            for (int half = 0; half < 2; half++) {
                const int ml = wm * 64 + i * 16 + mrow + half * 8;
#pragma unroll
                for (int j = 0; j < 8; j++) {
                    const int nl = wn * 64 + j * 8 + ncol;
                    *(float2*)(st + (size_t)ml * SROW + nl) =
                        make_float2(acc[i][j][half * 2], acc[i][j][half * 2 + 1]);
                }
            }
        }
        __syncthreads();
        const int atom0 = row0 / 3;
#pragma unroll 2
        for (int it = 0; it < 42; it++) {
            int idx = it * 256 + tid;          // 0..10751
            int ai = idx >> 8, o = idx & 255;
            int a = atom0 + ai;
            if (3 * a + 2 < p.M) {
                float x = st[(size_t)(3 * ai)     * SROW + o];
                float y = st[(size_t)(3 * ai + 1) * SROW + o];
                float z = st[(size_t)(3 * ai + 2) * SROW + o];
                float v = sqrtf(x * x + y * y + z * z);
                __nv_bfloat16 h, l;
                split_bf16(v, h, l);
                p.Oh[(size_t)a * 512 + 256 + o] = h;
                p.Ol[(size_t)a * 512 + 256 + o] = l;
            }
        }
        return;
    }

#pragma unroll
    for (int i = 0; i < 4; i++) {
        const int mbase = row0 + wm * 64 + i * 16 + mrow;
#pragma unroll
        for (int half = 0; half < 2; half++) {
            const int m = mbase + half * 8;
            if (m >= p.M) continue;
#pragma unroll
            for (int j = 0; j < 8; j++) {
                const int n = col0 + wn * 64 + j * 8 + ncol;
                float v0 = acc[i][j][half * 2 + 0];
                float v1 = acc[i][j][half * 2 + 1];
                if (EPI == 0) {
                    // vW tile (col0 == 256): fp32 -> C0 (ld 256)
                    *(float2*)(p.C0 + (size_t)m * 256 + (n - 256)) = make_float2(v0, v1);
                } else if (EPI == 1) {
                    v0 = silu_f(v0 + p.bias[n]);
                    v1 = silu_f(v1 + p.bias[n + 1]);
                    __nv_bfloat16 h0, l0, h1, l1;
                    split_bf16(v0, h0, l0);
                    split_bf16(v1, h1, l1);
                    *(__nv_bfloat162*)(p.Oh + (size_t)m * 256 + n) = __nv_bfloat162(h0, h1);
                    *(__nv_bfloat162*)(p.Ol + (size_t)m * 256 + n) = __nv_bfloat162(l0, l1);
                } else if (EPI == 2) {
                    v0 += p.bias[n];
                    v1 += p.bias[n + 1];
                    if (n < 256) {
                        v0 = silu_f(v0);
                        v1 = silu_f(v1);
                        __nv_bfloat16 h0, l0, h1, l1;
                        split_bf16(v0, h0, l0);
                        split_bf16(v1, h1, l1);
                        *(__nv_bfloat162*)(p.Oh + (size_t)m * 256 + n) = __nv_bfloat162(h0, h1);
                        *(__nv_bfloat162*)(p.Ol + (size_t)m * 256 + n) = __nv_bfloat162(l0, l1);
                    } else {
                        *(float2*)(p.C0 + (size_t)m * 256 + (n - 256)) = make_float2(v0, v1);
                    }
                } else {  // EPI 3
                    float um = p.u[m];
                    v0 = silu_f(v0 + um * p.vrow[n]     + p.bias[n]);
                    v1 = silu_f(v1 + um * p.vrow[n + 1] + p.bias[n + 1]);
                    *(float2*)(p.C0 + (size_t)m * 256 + n) = make_float2(v0, v1);
                }
            }
        }
    }
}

// ---------------------------------------------------------------------------
// conversions
// ---------------------------------------------------------------------------
__global__ void wt_conv(const float* __restrict__ W,
                        __nv_bfloat16* __restrict__ th,
                        __nv_bfloat16* __restrict__ tl, int K, int N) {
    int idx = blockIdx.x * blockDim.x + threadIdx.x;
    if (idx >= K * N) return;
    int k = idx / N, n = idx % N;
    __nv_bfloat16 h, l;
    split_bf16(W[idx], h, l);
    th[(size_t)n * K + k] = h;
    tl[(size_t)n * K + k] = l;
}

// float4-vectorized activation split: src [M, Ks] -> dst hi/lo [*, ldd]@coff
__global__ void act_conv4(const float4* __restrict__ src,
                          __nv_bfloat16* __restrict__ dh,
                          __nv_bfloat16* __restrict__ dl,
                          int M, int Ks4, int ldd, int coff) {
    int idx = blockIdx.x * blockDim.x + threadIdx.x;
    if (idx >= M * Ks4) return;
    int m = idx / Ks4, c = (idx - m * Ks4) * 4;
    float4 v = src[idx];
    __nv_bfloat16 h0, l0, h1, l1, h2, l2, h3, l3;
    split_bf16(v.x, h0, l0);
    split_bf16(v.y, h1, l1);
    split_bf16(v.z, h2, l2);
    split_bf16(v.w, h3, l3);
    size_t off = (size_t)m * ldd + coff + c;
    *(__nv_bfloat162*)(dh + off)     = __nv_bfloat162(h0, h1);
    *(__nv_bfloat162*)(dh + off + 2) = __nv_bfloat162(h2, h3);
    *(__nv_bfloat162*)(dl + off)     = __nv_bfloat162(l0, l1);
    *(__nv_bfloat162*)(dl + off + 2) = __nv_bfloat162(l2, l3);
}

// ---------------------------------------------------------------------------
// Block-2 glue
// ---------------------------------------------------------------------------
__global__ void stage2a_kernel(const float* __restrict__ vwbuf,
                               const float* __restrict__ gate,
                               const float* __restrict__ Wmix2,
                               float* __restrict__ vvn2,
                               float* __restrict__ vw2, int natoms) {
    __shared__ float sW[512];
    for (int i = threadIdx.x; i < 512; i += blockDim.x) sW[i] = Wmix2[i];
    __syncthreads();
    int warp = threadIdx.x >> 5, lane = threadIdx.x & 31;
    int m = blockIdx.x * 8 + warp;
    if (m >= natoms) return;
    const float* g  = gate + (size_t)m * 256;
    const float* vw = vwbuf + (size_t)3 * m * 256;
    float t00 = 0, t01 = 0, t10 = 0, t11 = 0, t20 = 0, t21 = 0;
#pragma unroll
    for (int i = 0; i < 8; i++) {
        int o = lane + 32 * i;
        float ga = g[o];
        float w0 = sW[2 * o], w1 = sW[2 * o + 1];
        float p0 = ga * vw[o];
        float p1 = ga * vw[256 + o];
        float p2 = ga * vw[512 + o];
        t00 += p0 * w0; t01 += p0 * w1;
        t10 += p1 * w0; t11 += p1 * w1;
        t20 += p2 * w0; t21 += p2 * w1;
    }
#pragma unroll
    for (int off = 16; off; off >>= 1) {
        t00 += __shfl_xor_sync(0xffffffffu, t00, off);
        t01 += __shfl_xor_sync(0xffffffffu, t01, off);
        t10 += __shfl_xor_sync(0xffffffffu, t10, off);
        t11 += __shfl_xor_sync(0xffffffffu, t11, off);
        t20 += __shfl_xor_sync(0xffffffffu, t20, off);
        t21 += __shfl_xor_sync(0xffffffffu, t21, off);
    }
    if (lane == 0) {
        vvn2[m] = sqrtf(t00 * t00 + t10 * t10 + t20 * t20);
        vw2[3 * m + 0] = t01;
        vw2[3 * m + 1] = t11;
        vw2[3 * m + 2] = t21;
    }
}

__global__ void stage2b_kernel(const float* __restrict__ h2,
                               const float* __restrict__ W2b,
                               const float* __restrict__ b2b,
                               const float* __restrict__ vw2,
                               const float* __restrict__ pos,
                               const int* __restrict__ batch,
                               float* __restrict__ out, int natoms, int nmol) {
    __shared__ float sW[512];
    for (int i = threadIdx.x; i < 512; i += blockDim.x) sW[i] = W2b[i];
    __syncthreads();
    int warp = threadIdx.x >> 5, lane = threadIdx.x & 31;
    int m = blockIdx.x * 8 + warp;
    if (m >= natoms) return;
    const float* h = h2 + (size_t)m * 256;
    float x0 = 0, x1 = 0;
#pragma unroll
    for (int i = 0; i < 8; i++) {
        int k = lane + 32 * i;
        float hv = h[k];
        x0 += hv * sW[2 * k];
        x1 += hv * sW[2 * k + 1];
    }
#pragma unroll
    for (int off = 16; off; off >>= 1) {
        x0 += __shfl_xor_sync(0xffffffffu, x0, off);
        x1 += __shfl_xor_sync(0xffffffffu, x1, off);
    }
    if (lane == 0) {
        float charge = x0 + b2b[0];
        float gate2  = x1 + b2b[1];
        int b = batch[m];
#pragma unroll
        for (int c = 0; c < 3; c++) {
            float v2 = gate2 * vw2[3 * m + c];
            float y  = v2 + pos[3 * m + c] * charge;
            atomicAdd(&out[(size_t)b * 3 + c], y);
            atomicAdd(&out[(size_t)nmol * 3 + (size_t)b * 3 + c], v2);
        }
    }
}

// ---------------------------------------------------------------------------
extern "C" void kernel_launch(void* const* d_in, const int* in_sizes, int n_in,
                              void* d_out, int out_size) {
    const float* pos   = (const float*)d_in[0];
    const float* l0    = (const float*)d_in[1];
    const float* l1    = (const float*)d_in[2];
    const int*   batch = (const int*)d_in[3];
    const float* Wmix1 = (const float*)d_in[4];
    const float* W1a   = (const float*)d_in[5];
    const float* b1a   = (const float*)d_in[6];
    const float* W2a   = (const float*)d_in[7];
    const float* b2a   = (const float*)d_in[8];
    const float* Wmix2 = (const float*)d_in[9];
    const float* W1b   = (const float*)d_in[10];
    const float* b1b   = (const float*)d_in[11];
    const float* W2b   = (const float*)d_in[12];
    const float* b2b   = (const float*)d_in[13];

    const int natoms = in_sizes[3];
    const int nmol   = out_size / 6;
    float* out = (float*)d_out;

    float *vw, *gate, *h2, *vvn2, *vw2;
    __nv_bfloat16 *a1h, *a1l, *a2h, *a2l, *a3h, *a3l, *a4h, *a4l;
    __nv_bfloat16 *bt1h, *bt1l, *bt2h, *bt2l, *bt3h, *bt3l, *bt4h, *bt4l;
    cudaGetSymbolAddress((void**)&vw,   g_vw);
    cudaGetSymbolAddress((void**)&gate, g_gate);
    cudaGetSymbolAddress((void**)&h2,   g_h2);
    cudaGetSymbolAddress((void**)&vvn2, g_vvn2);
    cudaGetSymbolAddress((void**)&vw2,  g_vw2);
    cudaGetSymbolAddress((void**)&a1h, g_a1h);  cudaGetSymbolAddress((void**)&a1l, g_a1l);
    cudaGetSymbolAddress((void**)&a2h, g_a2h);  cudaGetSymbolAddress((void**)&a2l, g_a2l);
    cudaGetSymbolAddress((void**)&a3h, g_a3h);  cudaGetSymbolAddress((void**)&a3l, g_a3l);
    cudaGetSymbolAddress((void**)&a4h, g_a4h);  cudaGetSymbolAddress((void**)&a4l, g_a4l);
    cudaGetSymbolAddress((void**)&bt1h, g_bt1h); cudaGetSymbolAddress((void**)&bt1l, g_bt1l);
    cudaGetSymbolAddress((void**)&bt2h, g_bt2h); cudaGetSymbolAddress((void**)&bt2l, g_bt2l);
    cudaGetSymbolAddress((void**)&bt3h, g_bt3h); cudaGetSymbolAddress((void**)&bt3l, g_bt3l);
    cudaGetSymbolAddress((void**)&bt4h, g_bt4h); cudaGetSymbolAddress((void**)&bt4l, g_bt4l);

    cudaFuncSetAttribute(gemm_mma<0>, cudaFuncAttributeMaxDynamicSharedMemorySize, SMEM_DYN);
    cudaFuncSetAttribute(gemm_mma<1>, cudaFuncAttributeMaxDynamicSharedMemorySize, SMEM_DYN);
    cudaFuncSetAttribute(gemm_mma<2>, cudaFuncAttributeMaxDynamicSharedMemorySize, SMEM_DYN);
    cudaFuncSetAttribute(gemm_mma<3>, cudaFuncAttributeMaxDynamicSharedMemorySize, SMEM_DYN);

    cudaMemsetAsync(d_out, 0, (size_t)out_size * sizeof(float));

    const int M1  = 3 * natoms;
    const int mt1 = (M1 + 125) / 126;          // GEMM1: 126-row tiles (42 atoms)
    const int mt  = (natoms + 127) / 128;

    // weight transposes + splits
    wt_conv<<<(256 * 512 + 255) / 256, 256>>>(Wmix1, bt1h, bt1l, 256, 512);
    wt_conv<<<(512 * 256 + 255) / 256, 256>>>(W1a,   bt2h, bt2l, 512, 256);
    wt_conv<<<(256 * 512 + 255) / 256, 256>>>(W2a,   bt3h, bt3l, 256, 512);
    wt_conv<<<(256 * 256 + 255) / 256, 256>>>(W1b,   bt4h, bt4l, 256, 256);

    // activation splits (float4 vectorized)
    act_conv4<<<(int)(((size_t)M1 * 64 + 255) / 256), 256>>>(
        (const float4*)l1, a1h, a1l, M1, 64, 256, 0);
    act_conv4<<<(int)(((size_t)natoms * 64 + 255) / 256), 256>>>(
        (const float4*)l0, a2h, a2l, natoms, 64, 512, 0);

    // GEMM1: vmix = l1 @ Wmix1 (3N x 512). col0=0 tile -> fused vVn norms into
    // a2 cols 256:512; col0=256 tile -> vW fp32 scratch.
    {
        MP p = {};
        p.Ah = a1h; p.Al = a1l; p.Bh = bt1h; p.Bl = bt1l;
        p.M = M1; p.K = 256; p.mstep = 126;
        p.C0 = vw; p.Oh = a2h; p.Ol = a2l;
        gemm_mma<0><<<dim3(2, mt1), 256, SMEM_DYN>>>(p);
    }

    // GEMM2: h = silu([l0|vVn] @ W1a + b1a) -> a3 (hi/lo)
    {
        MP p = {};
        p.Ah = a2h; p.Al = a2l; p.Bh = bt2h; p.Bl = bt2l;
        p.M = natoms; p.K = 512; p.mstep = 128;
        p.Oh = a3h; p.Ol = a3l; p.bias = b1a;
        gemm_mma<1><<<dim3(1, mt), 256, SMEM_DYN>>>(p);
    }

    // GEMM3: x = h @ W2a + b2a ; s1=silu(x[:,:256])->a4 ; gate=x[:,256:]
    {
        MP p = {};
        p.Ah = a3h; p.Al = a3l; p.Bh = bt3h; p.Bl = bt3l;
        p.M = natoms; p.K = 256; p.mstep = 128;
        p.Oh = a4h; p.Ol = a4l; p.C0 = gate; p.bias = b2a;
        gemm_mma<2><<<dim3(2, mt), 256, SMEM_DYN>>>(p);
    }

    // block-2 front: vvn2, vw2
    stage2a_kernel<<<(natoms + 7) / 8, 256>>>(vw, gate, Wmix2, vvn2, vw2, natoms);

    // GEMM4: h2 = silu(s1 @ W1b[:256] + vvn2*W1b[256] + b1b)
    {
        MP p = {};
        p.Ah = a4h; p.Al = a4l; p.Bh = bt4h; p.Bl = bt4l;
        p.M = natoms; p.K = 256; p.mstep = 128;
        p.C0 = h2; p.bias = b1b;
        p.u = vvn2; p.vrow = W1b + 256 * 256;
        gemm_mma<3><<<dim3(1, mt), 256, SMEM_DYN>>>(p);
    }

    // block-2 back + segment sums
    stage2b_kernel<<<(natoms + 7) / 8, 256>>>(h2, W2b, b2b, vw2, pos, batch,
                                              out, natoms, nmol);
}

// round 5
// speedup vs baseline: 3.1295x; 1.2349x over previous
#include <cuda_runtime.h>
#include <cuda_fp16.h>
#include <cstdint>
#include <cstddef>

// ---------------------------------------------------------------------------
// Dipole head: asymmetric fp16 2-pass GEMMs on mma.sync (HMMA), fp32 accum.
//   A = Ah + Al (fp16 split, residual ~2^-23); B = fp16(W) (delta ~2^-12).
//   A@B ~= Ah@B + Al@B  -> 2 MMA passes (was 3 bf16 passes).
// 128x256 CTA tiles, 3-stage cp.async ring, GEMM1-fused vector norms.
// ---------------------------------------------------------------------------

#define NA_MAX 200000
#define MPAD1  600128   // padded rows for GEMM1 (3*N atoms)
#define MPAD   200128   // padded rows for per-atom GEMMs

// ---------------- global scratch (zero-initialized at module load) ----------
__device__ __align__(128) float g_vw[(size_t)3 * NA_MAX * 256];   // vW fp32
__device__ __align__(128) __half g_a1h[(size_t)MPAD1 * 256];
__device__ __align__(128) __half g_a1l[(size_t)MPAD1 * 256];
__device__ __align__(128) __half g_a2h[(size_t)MPAD * 512];
__device__ __align__(128) __half g_a2l[(size_t)MPAD * 512];
__device__ __align__(128) __half g_a3h[(size_t)MPAD * 256];
__device__ __align__(128) __half g_a3l[(size_t)MPAD * 256];
__device__ __align__(128) __half g_a4h[(size_t)MPAD * 256];
__device__ __align__(128) __half g_a4l[(size_t)MPAD * 256];
__device__ __align__(128) float g_gate[(size_t)NA_MAX * 256];
__device__ __align__(128) float g_h2[(size_t)NA_MAX * 256];
__device__ float g_vvn2[NA_MAX];
__device__ float g_vw2[3 * NA_MAX];
__device__ __align__(128) __half g_bt1[512 * 256];
__device__ __align__(128) __half g_bt2[256 * 512];
__device__ __align__(128) __half g_bt3[512 * 256];
__device__ __align__(128) __half g_bt4[256 * 256];

// ---------------- helpers ----------------------------------------------
__device__ __forceinline__ uint32_t smem_u32(const void* p) {
    uint32_t a;
    asm("{ .reg .u64 t; cvta.to.shared.u64 t, %1; cvt.u32.u64 %0, t; }"
        : "=r"(a) : "l"(p));
    return a;
}
#define SWZ128(off) ((off) ^ (((off) >> 3) & 0x70))

__device__ __forceinline__ void cp16(uint32_t saddr, const void* gaddr) {
    asm volatile("cp.async.cg.shared.global [%0], [%1], 16;\n"
                 :: "r"(saddr), "l"(gaddr));
}
__device__ __forceinline__ void cp_commit() {
    asm volatile("cp.async.commit_group;\n" ::: "memory");
}

__device__ __forceinline__ void ldsm_x4(uint32_t* r, uint32_t a) {
    asm volatile("ldmatrix.sync.aligned.m8n8.x4.shared.b16 {%0,%1,%2,%3}, [%4];"
                 : "=r"(r[0]), "=r"(r[1]), "=r"(r[2]), "=r"(r[3]) : "r"(a));
}

__device__ __forceinline__ void mma16816(float* d, const uint32_t* a,
                                         const uint32_t* b) {
    asm volatile(
        "mma.sync.aligned.m16n8k16.row.col.f32.f16.f16.f32 "
        "{%0,%1,%2,%3}, {%4,%5,%6,%7}, {%8,%9}, {%0,%1,%2,%3};\n"
        : "+f"(d[0]), "+f"(d[1]), "+f"(d[2]), "+f"(d[3])
        : "r"(a[0]), "r"(a[1]), "r"(a[2]), "r"(a[3]), "r"(b[0]), "r"(b[1]));
}

__device__ __forceinline__ float silu_f(float x) { return x / (1.0f + __expf(-x)); }

__device__ __forceinline__ void split_f16(float v, __half& h, __half& l) {
    h = __float2half_rn(v);
    l = __float2half_rn(v - __half2float(h));
}

// ---------------------------------------------------------------------------
// HMMA GEMM, CTA tile 128x256, warp tile 64x64 (8 warps), K-chunk 64,
// 3-stage cp.async ring. 2-pass fp16 (Ah@B + Al@B), fp32 accumulate.
// EPI 0: GEMM1 special — col0==0: vector norms -> Oh/Ol cols 256:512;
//        col0==256: vW fp32 -> C0 (ld 256)
// EPI 1: silu(v+bias) -> fp16 hi/lo (ld 256)
// EPI 2: n<256: silu(v+bias)->hi/lo ; n>=256: v+bias -> C0 fp32 (ld 256)
// EPI 3: silu(v + u[m]*vrow[n] + bias) -> C0 fp32 (ld 256)
// ---------------------------------------------------------------------------
struct MP {
    const __half *Ah, *Al;
    const __half *B;
    int M;        // real rows (epilogue guard)
    int K;        // multiple of 64
    int mstep;    // row tile stride (128, or 126 for GEMM1)
    float *C0;
    __half *Oh, *Ol;
    const float *bias, *u, *vrow;
};

#define OFF_AL 16384
#define OFF_B  32768
#define STG    65536
#define SMEM_DYN (3 * STG)
#define SROW 264   // fp32 smem tile row stride (epilogue norm path)

template <int EPI>
__global__ void __launch_bounds__(256, 1) gemm_mma(const MP p) {
    extern __shared__ __align__(1024) char smem[];
    const uint32_t sb = smem_u32(smem);
    const int tid  = threadIdx.x;
    const int wid  = tid >> 5;
    const int lane = tid & 31;
    const int wm   = wid >> 2;   // 0..1  (64-row slab)
    const int wn   = wid & 3;    // 0..3  (64-col slab)
    const int row0 = blockIdx.y * p.mstep;
    const int col0 = blockIdx.x * 256;

    // ldmatrix per-lane address components
    const int      rA0 = wm * 64 + (lane & 7) + ((lane >> 3) & 1) * 8;
    const uint32_t xA  = (uint32_t)(rA0 & 7) << 4;
    const uint32_t kA  = (uint32_t)(lane >> 4) * 16;
    const int      rB0 = wn * 64 + ((lane >> 4) * 8) + (lane & 7);
    const uint32_t xB  = (uint32_t)(rB0 & 7) << 4;
    const uint32_t kB  = (uint32_t)((lane >> 3) & 1) * 16;

    float acc[4][8][4];
#pragma unroll
    for (int i = 0; i < 4; i++)
#pragma unroll
        for (int j = 0; j < 8; j++)
#pragma unroll
            for (int q = 0; q < 4; q++) acc[i][j][q] = 0.f;

    const int NC = p.K >> 6;   // 64-wide K chunks

    auto load_chunk = [&](int kc, int s) {
        const uint32_t base = sb + s * STG;
        const int koff = kc * 64;
#pragma unroll
        for (int i = 0; i < 4; i++) {          // A: 128 rows x 128B (hi+lo)
            int idx = i * 256 + tid;
            int r = idx >> 3, ch = idx & 7;
            uint32_t so = SWZ128((uint32_t)(r * 128 + ch * 16));
            size_t ga = (size_t)(row0 + r) * p.K + koff + ch * 8;
            cp16(base + so,          p.Ah + ga);
            cp16(base + OFF_AL + so, p.Al + ga);
        }
#pragma unroll
        for (int i = 0; i < 8; i++) {          // B: 256 rows x 128B
            int idx = i * 256 + tid;
            int r = idx >> 3, ch = idx & 7;
            uint32_t so = SWZ128((uint32_t)(r * 128 + ch * 16));
            size_t gb = (size_t)(col0 + r) * p.K + koff + ch * 8;
            cp16(base + OFF_B + so, p.B + gb);
        }
        cp_commit();
    };

    load_chunk(0, 0);
    if (NC > 1) load_chunk(1, 1);

    for (int c = 0; c < NC; c++) {
        const int s = c % 3;
        if (c + 1 < NC) asm volatile("cp.async.wait_group 1;\n" ::: "memory");
        else            asm volatile("cp.async.wait_group 0;\n" ::: "memory");
        __syncthreads();

        const uint32_t base = sb + s * STG;
#pragma unroll
        for (int ks = 0; ks < 4; ks++) {
            const uint32_t kbA = ((uint32_t)(ks * 32) + kA) ^ xA;
            const uint32_t kbB = ((uint32_t)(ks * 32) + kB) ^ xB;
            uint32_t Ah4[4][4], Al4[4][4];
#pragma unroll
            for (int i = 0; i < 4; i++) {
                uint32_t ro = (uint32_t)(rA0 + i * 16) * 128;
                ldsm_x4(Ah4[i], base + ro + kbA);
                ldsm_x4(Al4[i], base + OFF_AL + ro + kbA);
            }
#pragma unroll
            for (int jp = 0; jp < 4; jp++) {
                uint32_t ro = (uint32_t)(rB0 + jp * 16) * 128;
                uint32_t bb[4];
                ldsm_x4(bb, base + OFF_B + ro + kbB);
#pragma unroll
                for (int i = 0; i < 4; i++) {
                    mma16816(acc[i][2 * jp],     Ah4[i], bb);
                    mma16816(acc[i][2 * jp + 1], Ah4[i], bb + 2);
                    mma16816(acc[i][2 * jp],     Al4[i], bb);
                    mma16816(acc[i][2 * jp + 1], Al4[i], bb + 2);
                }
            }
        }
        __syncthreads();
        if (c + 2 < NC) load_chunk(c + 2, (c + 2) % 3);
    }

    // ---------------- epilogue ----------------
    const int mrow = lane >> 2;          // 0..7
    const int ncol = (lane & 3) * 2;     // 0,2,4,6

    if (EPI == 0 && col0 == 0) {
        // vV tile: stage fp32 accumulators to smem, then compute norms.
        float* st = (float*)smem;
#pragma unroll
        for (int i = 0; i < 4; i++) {
#pragma unroll
            for (int half = 0; half < 2; half++) {
                const int ml = wm * 64 + i * 16 + mrow + half * 8;
#pragma unroll
                for (int j = 0; j < 8; j++) {
                    const int nl = wn * 64 + j * 8 + ncol;
                    *(float2*)(st + (size_t)ml * SROW + nl) =
                        make_float2(acc[i][j][half * 2], acc[i][j][half * 2 + 1]);
                }
            }
        }
        __syncthreads();
        const int atom0 = row0 / 3;
#pragma unroll 2
        for (int it = 0; it < 42; it++) {
            int idx = it * 256 + tid;          // 0..10751
            int ai = idx >> 8, o = idx & 255;
            int a = atom0 + ai;
            if (3 * a + 2 < p.M) {
                float x = st[(size_t)(3 * ai)     * SROW + o];
                float y = st[(size_t)(3 * ai + 1) * SROW + o];
                float z = st[(size_t)(3 * ai + 2) * SROW + o];
                float v = sqrtf(x * x + y * y + z * z);
                __half h, l;
                split_f16(v, h, l);
                p.Oh[(size_t)a * 512 + 256 + o] = h;
                p.Ol[(size_t)a * 512 + 256 + o] = l;
            }
        }
        return;
    }

#pragma unroll
    for (int i = 0; i < 4; i++) {
        const int mbase = row0 + wm * 64 + i * 16 + mrow;
#pragma unroll
        for (int half = 0; half < 2; half++) {
            const int m = mbase + half * 8;
            if (m >= p.M) continue;
#pragma unroll
            for (int j = 0; j < 8; j++) {
                const int n = col0 + wn * 64 + j * 8 + ncol;
                float v0 = acc[i][j][half * 2 + 0];
                float v1 = acc[i][j][half * 2 + 1];
                if (EPI == 0) {
                    // vW tile (col0 == 256): fp32 -> C0 (ld 256)
                    *(float2*)(p.C0 + (size_t)m * 256 + (n - 256)) = make_float2(v0, v1);
                } else if (EPI == 1) {
                    v0 = silu_f(v0 + p.bias[n]);
                    v1 = silu_f(v1 + p.bias[n + 1]);
                    __half h0, l0, h1, l1;
                    split_f16(v0, h0, l0);
                    split_f16(v1, h1, l1);
                    *(__half2*)(p.Oh + (size_t)m * 256 + n) = __half2(h0, h1);
                    *(__half2*)(p.Ol + (size_t)m * 256 + n) = __half2(l0, l1);
                } else if (EPI == 2) {
                    v0 += p.bias[n];
                    v1 += p.bias[n + 1];
                    if (n < 256) {
                        v0 = silu_f(v0);
                        v1 = silu_f(v1);
                        __half h0, l0, h1, l1;
                        split_f16(v0, h0, l0);
                        split_f16(v1, h1, l1);
                        *(__half2*)(p.Oh + (size_t)m * 256 + n) = __half2(h0, h1);
                        *(__half2*)(p.Ol + (size_t)m * 256 + n) = __half2(l0, l1);
                    } else {
                        *(float2*)(p.C0 + (size_t)m * 256 + (n - 256)) = make_float2(v0, v1);
                    }
                } else {  // EPI 3
                    float um = p.u[m];
                    v0 = silu_f(v0 + um * p.vrow[n]     + p.bias[n]);
                    v1 = silu_f(v1 + um * p.vrow[n + 1] + p.bias[n + 1]);
                    *(float2*)(p.C0 + (size_t)m * 256 + n) = make_float2(v0, v1);
                }
            }
        }
    }
}

// ---------------------------------------------------------------------------
// conversions
// ---------------------------------------------------------------------------
// weights: W [K,N] fp32 -> transposed fp16 [N,K]
__global__ void wt_conv(const float* __restrict__ W,
                        __half* __restrict__ t, int K, int N) {
    int idx = blockIdx.x * blockDim.x + threadIdx.x;
    if (idx >= K * N) return;
    int k = idx / N, n = idx % N;
    t[(size_t)n * K + k] = __float2half_rn(W[idx]);
}

// float4-vectorized activation split: src [M, Ks] -> dst hi/lo [*, ldd]@coff
__global__ void act_conv4(const float4* __restrict__ src,
                          __half* __restrict__ dh,
                          __half* __restrict__ dl,
                          int M, int Ks4, int ldd, int coff) {
    int idx = blockIdx.x * blockDim.x + threadIdx.x;
    if (idx >= M * Ks4) return;
    int m = idx / Ks4, c = (idx - m * Ks4) * 4;
    float4 v = src[idx];
    __half h0, l0, h1, l1, h2, l2, h3, l3;
    split_f16(v.x, h0, l0);
    split_f16(v.y, h1, l1);
    split_f16(v.z, h2, l2);
    split_f16(v.w, h3, l3);
    size_t off = (size_t)m * ldd + coff + c;
    *(__half2*)(dh + off)     = __half2(h0, h1);
    *(__half2*)(dh + off + 2) = __half2(h2, h3);
    *(__half2*)(dl + off)     = __half2(l0, l1);
    *(__half2*)(dl + off + 2) = __half2(l2, l3);
}

// ---------------------------------------------------------------------------
// Block-2 glue
// ---------------------------------------------------------------------------
__global__ void stage2a_kernel(const float* __restrict__ vwbuf,
                               const float* __restrict__ gate,
                               const float* __restrict__ Wmix2,
                               float* __restrict__ vvn2,
                               float* __restrict__ vw2, int natoms) {
    __shared__ float sW[512];
    for (int i = threadIdx.x; i < 512; i += blockDim.x) sW[i] = Wmix2[i];
    __syncthreads();
    int warp = threadIdx.x >> 5, lane = threadIdx.x & 31;
    int m = blockIdx.x * 8 + warp;
    if (m >= natoms) return;
    const float* g  = gate + (size_t)m * 256;
    const float* vw = vwbuf + (size_t)3 * m * 256;
    float t00 = 0, t01 = 0, t10 = 0, t11 = 0, t20 = 0, t21 = 0;
#pragma unroll
    for (int i = 0; i < 8; i++) {
        int o = lane + 32 * i;
        float ga = g[o];
        float w0 = sW[2 * o], w1 = sW[2 * o + 1];
        float p0 = ga * vw[o];
        float p1 = ga * vw[256 + o];
        float p2 = ga * vw[512 + o];
        t00 += p0 * w0; t01 += p0 * w1;
        t10 += p1 * w0; t11 += p1 * w1;
        t20 += p2 * w0; t21 += p2 * w1;
    }
#pragma unroll
    for (int off = 16; off; off >>= 1) {
        t00 += __shfl_xor_sync(0xffffffffu, t00, off);
        t01 += __shfl_xor_sync(0xffffffffu, t01, off);
        t10 += __shfl_xor_sync(0xffffffffu, t10, off);
        t11 += __shfl_xor_sync(0xffffffffu, t11, off);
        t20 += __shfl_xor_sync(0xffffffffu, t20, off);
        t21 += __shfl_xor_sync(0xffffffffu, t21, off);
    }
    if (lane == 0) {
        vvn2[m] = sqrtf(t00 * t00 + t10 * t10 + t20 * t20);
        vw2[3 * m + 0] = t01;
        vw2[3 * m + 1] = t11;
        vw2[3 * m + 2] = t21;
    }
}

__global__ void stage2b_kernel(const float* __restrict__ h2,
                               const float* __restrict__ W2b,
                               const float* __restrict__ b2b,
                               const float* __restrict__ vw2,
                               const float* __restrict__ pos,
                               const int* __restrict__ batch,
                               float* __restrict__ out, int natoms, int nmol) {
    __shared__ float sW[512];
    for (int i = threadIdx.x; i < 512; i += blockDim.x) sW[i] = W2b[i];
    __syncthreads();
    int warp = threadIdx.x >> 5, lane = threadIdx.x & 31;
    int m = blockIdx.x * 8 + warp;
    if (m >= natoms) return;
    const float* h = h2 + (size_t)m * 256;
    float x0 = 0, x1 = 0;
#pragma unroll
    for (int i = 0; i < 8; i++) {
        int k = lane + 32 * i;
        float hv = h[k];
        x0 += hv * sW[2 * k];
        x1 += hv * sW[2 * k + 1];
    }
#pragma unroll
    for (int off = 16; off; off >>= 1) {
        x0 += __shfl_xor_sync(0xffffffffu, x0, off);
        x1 += __shfl_xor_sync(0xffffffffu, x1, off);
    }
    if (lane == 0) {
        float charge = x0 + b2b[0];
        float gate2  = x1 + b2b[1];
        int b = batch[m];
#pragma unroll
        for (int c = 0; c < 3; c++) {
            float v2 = gate2 * vw2[3 * m + c];
            float y  = v2 + pos[3 * m + c] * charge;
            atomicAdd(&out[(size_t)b * 3 + c], y);
            atomicAdd(&out[(size_t)nmol * 3 + (size_t)b * 3 + c], v2);
        }
    }
}

// ---------------------------------------------------------------------------
extern "C" void kernel_launch(void* const* d_in, const int* in_sizes, int n_in,
                              void* d_out, int out_size) {
    const float* pos   = (const float*)d_in[0];
    const float* l0    = (const float*)d_in[1];
    const float* l1    = (const float*)d_in[2];
    const int*   batch = (const int*)d_in[3];
    const float* Wmix1 = (const float*)d_in[4];
    const float* W1a   = (const float*)d_in[5];
    const float* b1a   = (const float*)d_in[6];
    const float* W2a   = (const float*)d_in[7];
    const float* b2a   = (const float*)d_in[8];
    const float* Wmix2 = (const float*)d_in[9];
    const float* W1b   = (const float*)d_in[10];
    const float* b1b   = (const float*)d_in[11];
    const float* W2b   = (const float*)d_in[12];
    const float* b2b   = (const float*)d_in[13];

    const int natoms = in_sizes[3];
    const int nmol   = out_size / 6;
    float* out = (float*)d_out;

    float *vw, *gate, *h2, *vvn2, *vw2;
    __half *a1h, *a1l, *a2h, *a2l, *a3h, *a3l, *a4h, *a4l;
    __half *bt1, *bt2, *bt3, *bt4;
    cudaGetSymbolAddress((void**)&vw,   g_vw);
    cudaGetSymbolAddress((void**)&gate, g_gate);
    cudaGetSymbolAddress((void**)&h2,   g_h2);
    cudaGetSymbolAddress((void**)&vvn2, g_vvn2);
    cudaGetSymbolAddress((void**)&vw2,  g_vw2);
    cudaGetSymbolAddress((void**)&a1h, g_a1h);  cudaGetSymbolAddress((void**)&a1l, g_a1l);
    cudaGetSymbolAddress((void**)&a2h, g_a2h);  cudaGetSymbolAddress((void**)&a2l, g_a2l);
    cudaGetSymbolAddress((void**)&a3h, g_a3h);  cudaGetSymbolAddress((void**)&a3l, g_a3l);
    cudaGetSymbolAddress((void**)&a4h, g_a4h);  cudaGetSymbolAddress((void**)&a4l, g_a4l);
    cudaGetSymbolAddress((void**)&bt1, g_bt1);
    cudaGetSymbolAddress((void**)&bt2, g_bt2);
    cudaGetSymbolAddress((void**)&bt3, g_bt3);
    cudaGetSymbolAddress((void**)&bt4, g_bt4);

    cudaFuncSetAttribute(gemm_mma<0>, cudaFuncAttributeMaxDynamicSharedMemorySize, SMEM_DYN);
    cudaFuncSetAttribute(gemm_mma<1>, cudaFuncAttributeMaxDynamicSharedMemorySize, SMEM_DYN);
    cudaFuncSetAttribute(gemm_mma<2>, cudaFuncAttributeMaxDynamicSharedMemorySize, SMEM_DYN);
    cudaFuncSetAttribute(gemm_mma<3>, cudaFuncAttributeMaxDynamicSharedMemorySize, SMEM_DYN);

    cudaMemsetAsync(d_out, 0, (size_t)out_size * sizeof(float));

    const int M1  = 3 * natoms;
    const int mt1 = (M1 + 125) / 126;          // GEMM1: 126-row tiles (42 atoms)
    const int mt  = (natoms + 127) / 128;

    // weight transposes (single fp16)
    wt_conv<<<(256 * 512 + 255) / 256, 256>>>(Wmix1, bt1, 256, 512);
    wt_conv<<<(512 * 256 + 255) / 256, 256>>>(W1a,   bt2, 512, 256);
    wt_conv<<<(256 * 512 + 255) / 256, 256>>>(W2a,   bt3, 256, 512);
    wt_conv<<<(256 * 256 + 255) / 256, 256>>>(W1b,   bt4, 256, 256);

    // activation splits (float4 vectorized)
    act_conv4<<<(int)(((size_t)M1 * 64 + 255) / 256), 256>>>(
        (const float4*)l1, a1h, a1l, M1, 64, 256, 0);
    act_conv4<<<(int)(((size_t)natoms * 64 + 255) / 256), 256>>>(
        (const float4*)l0, a2h, a2l, natoms, 64, 512, 0);

    // GEMM1: vmix = l1 @ Wmix1 (3N x 512). col0=0 tile -> fused vVn norms into
    // a2 cols 256:512; col0=256 tile -> vW fp32 scratch.
    {
        MP p = {};
        p.Ah = a1h; p.Al = a1l; p.B = bt1;
        p.M = M1; p.K = 256; p.mstep = 126;
        p.C0 = vw; p.Oh = a2h; p.Ol = a2l;
        gemm_mma<0><<<dim3(2, mt1), 256, SMEM_DYN>>>(p);
    }

    // GEMM2: h = silu([l0|vVn] @ W1a + b1a) -> a3 (hi/lo)
    {
        MP p = {};
        p.Ah = a2h; p.Al = a2l; p.B = bt2;
        p.M = natoms; p.K = 512; p.mstep = 128;
        p.Oh = a3h; p.Ol = a3l; p.bias = b1a;
        gemm_mma<1><<<dim3(1, mt), 256, SMEM_DYN>>>(p);
    }

    // GEMM3: x = h @ W2a + b2a ; s1=silu(x[:,:256])->a4 ; gate=x[:,256:]
    {
        MP p = {};
        p.Ah = a3h; p.Al = a3l; p.B = bt3;
        p.M = natoms; p.K = 256; p.mstep = 128;
        p.Oh = a4h; p.Ol = a4l; p.C0 = gate; p.bias = b2a;
        gemm_mma<2><<<dim3(2, mt), 256, SMEM_DYN>>>(p);
    }

    // block-2 front: vvn2, vw2
    stage2a_kernel<<<(natoms + 7) / 8, 256>>>(vw, gate, Wmix2, vvn2, vw2, natoms);

    // GEMM4: h2 = silu(s1 @ W1b[:256] + vvn2*W1b[256] + b1b)
    {
        MP p = {};
        p.Ah = a4h; p.Al = a4l; p.B = bt4;
        p.M = natoms; p.K = 256; p.mstep = 128;
        p.C0 = h2; p.bias = b1b;
        p.u = vvn2; p.vrow = W1b + 256 * 256;
        gemm_mma<3><<<dim3(1, mt), 256, SMEM_DYN>>>(p);
    }

    // block-2 back + segment sums
    stage2b_kernel<<<(natoms + 7) / 8, 256>>>(h2, W2b, b2b, vw2, pos, batch,
                                              out, natoms, nmol);
}

// round 6
// speedup vs baseline: 3.3473x; 1.0696x over previous
#include <cuda_runtime.h>
#include <cuda_fp16.h>
#include <cstdint>
#include <cstddef>

// ---------------------------------------------------------------------------
// Dipole head: asymmetric fp16 2-pass GEMMs on mma.sync (HMMA), fp32 accum.
// R6: fp32->fp16 split fused into GEMM loaders (act_conv gone), stage2a fused
//     into GEMM3 epilogue, stage2b fused into GEMM4 epilogue, 1 barrier/chunk.
// GEMM arithmetic identical to R5 (rel_err must stay ~6.4e-4).
// ---------------------------------------------------------------------------

#define NA_MAX 200000
#define MPAD   200128   // padded rows for per-atom fp16 activation buffers

// ---------------- global scratch (zero-initialized at module load) ----------
__device__ __align__(128) float g_vw[(size_t)3 * NA_MAX * 256];   // vW fp32
__device__ __align__(128) __half g_a2h[(size_t)MPAD * 512];
__device__ __align__(128) __half g_a2l[(size_t)MPAD * 512];
__device__ __align__(128) __half g_a3h[(size_t)MPAD * 256];
__device__ __align__(128) __half g_a3l[(size_t)MPAD * 256];
__device__ __align__(128) __half g_a4h[(size_t)MPAD * 256];
__device__ __align__(128) __half g_a4l[(size_t)MPAD * 256];
__device__ float g_vvn2[NA_MAX];
__device__ float g_vw2[3 * NA_MAX];
__device__ __align__(128) __half g_bt1[512 * 256];
__device__ __align__(128) __half g_bt2[256 * 512];
__device__ __align__(128) __half g_bt3[512 * 256];
__device__ __align__(128) __half g_bt4[256 * 256];

// ---------------- helpers ----------------------------------------------
__device__ __forceinline__ uint32_t smem_u32(const void* p) {
    uint32_t a;
    asm("{ .reg .u64 t; cvta.to.shared.u64 t, %1; cvt.u32.u64 %0, t; }"
        : "=r"(a) : "l"(p));
    return a;
}
#define SWZ128(off) ((off) ^ (((off) >> 3) & 0x70))

__device__ __forceinline__ void cp16(uint32_t saddr, const void* gaddr) {
    asm volatile("cp.async.cg.shared.global [%0], [%1], 16;\n"
                 :: "r"(saddr), "l"(gaddr));
}
__device__ __forceinline__ void cp_commit() {
    asm volatile("cp.async.commit_group;\n" ::: "memory");
}

__device__ __forceinline__ void ldsm_x4(uint32_t* r, uint32_t a) {
    asm volatile("ldmatrix.sync.aligned.m8n8.x4.shared.b16 {%0,%1,%2,%3}, [%4];"
                 : "=r"(r[0]), "=r"(r[1]), "=r"(r[2]), "=r"(r[3]) : "r"(a));
}

__device__ __forceinline__ void mma16816(float* d, const uint32_t* a,
                                         const uint32_t* b) {
    asm volatile(
        "mma.sync.aligned.m16n8k16.row.col.f32.f16.f16.f32 "
        "{%0,%1,%2,%3}, {%4,%5,%6,%7}, {%8,%9}, {%0,%1,%2,%3};\n"
        : "+f"(d[0]), "+f"(d[1]), "+f"(d[2]), "+f"(d[3])
        : "r"(a[0]), "r"(a[1]), "r"(a[2]), "r"(a[3]), "r"(b[0]), "r"(b[1]));
}

__device__ __forceinline__ float silu_f(float x) { return x / (1.0f + __expf(-x)); }

__device__ __forceinline__ void split_f16(float v, __half& h, __half& l) {
    h = __float2half_rn(v);
    l = __float2half_rn(v - __half2float(h));
}

// ---------------------------------------------------------------------------
// HMMA GEMM, CTA tile 128x256, warp tile 64x64 (8 warps), K-chunk 64,
// 2-stage ring with in-loader fp32->fp16 hi/lo conversion for k < ksplit.
// EPI 0: GEMM1 — col0==0: vector norms -> Oh/Ol cols 256:512;
//        col0==256: vW fp32 -> C0 (ld 256)
// EPI 1: silu(v+bias) -> fp16 hi/lo (ld 256)
// EPI 2: col0==0: silu(v+bias)->hi/lo ; col0==256: gate=v+bias -> fused
//        stage2a (vvn2, vw2)
// EPI 3: h2 = silu(v + u[m]*vrow[n] + bias) -> fused stage2b (segment sums)
// ---------------------------------------------------------------------------
struct MP {
    const float*  Af;        // fp32 A source for k < ksplit
    int           ldaf;
    const __half *Ah, *Al;   // fp16 A source for k >= ksplit
    int           ldah, coffh;
    const __half *B;
    int M, K, ksplit, mstep;
    float *C0;
    __half *Oh, *Ol;
    const float *bias, *u, *vrow;
    // fused stage2a (EPI 2):
    const float *vw, *Wmix2;
    float *vvn2, *vw2;
    // fused stage2b (EPI 3):
    const float *W2b, *b2b, *pos;
    const int *batch;
    float *out;
    int nmol;
};

#define OFF_AL  16384
#define OFF_B   32768
#define OFF_F32 65536
#define STG     98304
#define SMEM_DYN (2 * STG)
#define SROW 264   // fp32 smem tile row stride (fused epilogues)

template <int EPI>
__global__ void __launch_bounds__(256, 1) gemm_mma(const MP p) {
    extern __shared__ __align__(1024) char smem[];
    const uint32_t sb = smem_u32(smem);
    const int tid  = threadIdx.x;
    const int wid  = tid >> 5;
    const int lane = tid & 31;
    const int wm   = wid >> 2;   // 0..1  (64-row slab)
    const int wn   = wid & 3;    // 0..3  (64-col slab)
    const int row0 = blockIdx.y * p.mstep;
    const int col0 = blockIdx.x * 256;

    // ldmatrix per-lane address components
    const int      rA0 = wm * 64 + (lane & 7) + ((lane >> 3) & 1) * 8;
    const uint32_t xA  = (uint32_t)(rA0 & 7) << 4;
    const uint32_t kA  = (uint32_t)(lane >> 4) * 16;
    const int      rB0 = wn * 64 + ((lane >> 4) * 8) + (lane & 7);
    const uint32_t xB  = (uint32_t)(rB0 & 7) << 4;
    const uint32_t kB  = (uint32_t)((lane >> 3) & 1) * 16;

    float acc[4][8][4];
#pragma unroll
    for (int i = 0; i < 4; i++)
#pragma unroll
        for (int j = 0; j < 8; j++)
#pragma unroll
            for (int q = 0; q < 4; q++) acc[i][j][q] = 0.f;

    const int NC = p.K >> 6;   // 64-wide K chunks

    auto load_chunk = [&](int kc, int s) {
        const uint32_t base = sb + s * STG;
        const int koff = kc * 64;
        if (koff < p.ksplit) {
            // fp32 A chunk -> staging buffer (linear, 256 B/row)
#pragma unroll
            for (int i = 0; i < 8; i++) {
                int idx = i * 256 + tid;
                int r = idx >> 4, u = idx & 15;
                int gr = row0 + r;
                if (gr > p.M - 1) gr = p.M - 1;
                cp16(base + OFF_F32 + (uint32_t)(r * 256 + u * 16),
                     p.Af + (size_t)gr * p.ldaf + koff + u * 4);
            }
        } else {
            // fp16 hi/lo A chunk -> swizzled tiles
#pragma unroll
            for (int i = 0; i < 4; i++) {
                int idx = i * 256 + tid;
                int r = idx >> 3, ch = idx & 7;
                uint32_t so = SWZ128((uint32_t)(r * 128 + ch * 16));
                int gr = row0 + r;
                if (gr > p.M - 1) gr = p.M - 1;
                size_t ga = (size_t)gr * p.ldah + p.coffh + (koff - p.ksplit) + ch * 8;
                cp16(base + so,          p.Ah + ga);
                cp16(base + OFF_AL + so, p.Al + ga);
            }
        }
#pragma unroll
        for (int i = 0; i < 8; i++) {
            int idx = i * 256 + tid;
            int r = idx >> 3, ch = idx & 7;
            uint32_t so = SWZ128((uint32_t)(r * 128 + ch * 16));
            size_t gb = (size_t)(col0 + r) * p.K + koff + ch * 8;
            cp16(base + OFF_B + so, p.B + gb);
        }
        cp_commit();
    };

    auto convert_stage = [&](int s) {
        char* stg = smem + s * STG;
#pragma unroll
        for (int i = 0; i < 4; i++) {
            int idx = i * 256 + tid;
            int r = idx >> 3, ch = idx & 7;
            const float* src = (const float*)(stg + OFF_F32 + r * 256 + ch * 32);
            float4 a = *(const float4*)(src);
            float4 b = *(const float4*)(src + 4);
            float f[8] = {a.x, a.y, a.z, a.w, b.x, b.y, b.z, b.w};
            __half hh[8], ll[8];
#pragma unroll
            for (int q = 0; q < 8; q++) split_f16(f[q], hh[q], ll[q]);
            uint32_t so = SWZ128((uint32_t)(r * 128 + ch * 16));
            *(uint4*)(stg + so)          = *(const uint4*)hh;
            *(uint4*)(stg + OFF_AL + so) = *(const uint4*)ll;
        }
    };

    load_chunk(0, 0);

    for (int c = 0; c < NC; c++) {
        const int s = c & 1;
        asm volatile("cp.async.wait_group 0;\n" ::: "memory");
        __syncthreads();
        if (c + 1 < NC) load_chunk(c + 1, s ^ 1);
        if ((c << 6) < p.ksplit) {
            convert_stage(s);
            __syncthreads();
        }

        const uint32_t base = sb + s * STG;
#pragma unroll
        for (int ks = 0; ks < 4; ks++) {
            const uint32_t kbA = ((uint32_t)(ks * 32) + kA) ^ xA;
            const uint32_t kbB = ((uint32_t)(ks * 32) + kB) ^ xB;
            uint32_t Ah4[4][4], Al4[4][4];
#pragma unroll
            for (int i = 0; i < 4; i++) {
                uint32_t ro = (uint32_t)(rA0 + i * 16) * 128;
                ldsm_x4(Ah4[i], base + ro + kbA);
                ldsm_x4(Al4[i], base + OFF_AL + ro + kbA);
            }
#pragma unroll
            for (int jp = 0; jp < 4; jp++) {
                uint32_t ro = (uint32_t)(rB0 + jp * 16) * 128;
                uint32_t bb[4];
                ldsm_x4(bb, base + OFF_B + ro + kbB);
#pragma unroll
                for (int i = 0; i < 4; i++) {
                    mma16816(acc[i][2 * jp],     Ah4[i], bb);
                    mma16816(acc[i][2 * jp + 1], Ah4[i], bb + 2);
                    mma16816(acc[i][2 * jp],     Al4[i], bb);
                    mma16816(acc[i][2 * jp + 1], Al4[i], bb + 2);
                }
            }
        }
    }
    __syncthreads();   // retire smem tiles before epilogue reuse

    // ---------------- epilogue ----------------
    const int mrow = lane >> 2;          // 0..7
    const int ncol = (lane & 3) * 2;     // 0,2,4,6
    float* st = (float*)smem;
    float* sW = st + 128 * SROW;

    if (EPI == 0 && col0 == 0) {
        // GEMM1 vV tile: stage accumulators, compute per-atom norms.
#pragma unroll
        for (int i = 0; i < 4; i++)
#pragma unroll
            for (int half = 0; half < 2; half++) {
                const int ml = wm * 64 + i * 16 + mrow + half * 8;
#pragma unroll
                for (int j = 0; j < 8; j++) {
                    const int nl = wn * 64 + j * 8 + ncol;
                    *(float2*)(st + (size_t)ml * SROW + nl) =
                        make_float2(acc[i][j][half * 2], acc[i][j][half * 2 + 1]);
                }
            }
        __syncthreads();
        const int atom0 = row0 / 3;
#pragma unroll 2
        for (int it = 0; it < 42; it++) {
            int idx = it * 256 + tid;
            int ai = idx >> 8, o = idx & 255;
            int a = atom0 + ai;
            if (3 * a + 2 < p.M) {
                float x = st[(size_t)(3 * ai)     * SROW + o];
                float y = st[(size_t)(3 * ai + 1) * SROW + o];
                float z = st[(size_t)(3 * ai + 2) * SROW + o];
                float v = sqrtf(x * x + y * y + z * z);
                __half h, l;
                split_f16(v, h, l);
                p.Oh[(size_t)a * 512 + 256 + o] = h;
                p.Ol[(size_t)a * 512 + 256 + o] = l;
            }
        }
        return;
    }

    if (EPI == 2 && col0 == 256) {
        // gate tile -> smem, then fused stage2a.
#pragma unroll
        for (int i = 0; i < 4; i++)
#pragma unroll
            for (int half = 0; half < 2; half++) {
                const int ml = wm * 64 + i * 16 + mrow + half * 8;
#pragma unroll
                for (int j = 0; j < 8; j++) {
                    const int nl = wn * 64 + j * 8 + ncol;
                    float v0 = acc[i][j][half * 2]     + p.bias[256 + nl];
                    float v1 = acc[i][j][half * 2 + 1] + p.bias[256 + nl + 1];
                    *(float2*)(st + (size_t)ml * SROW + nl) = make_float2(v0, v1);
                }
            }
        sW[tid] = p.Wmix2[tid];
        sW[256 + tid] = p.Wmix2[256 + tid];
        __syncthreads();
#pragma unroll 1
        for (int t = 0; t < 16; t++) {
            const int ml = wid * 16 + t;
            const int m  = row0 + ml;
            float t00 = 0, t01 = 0, t10 = 0, t11 = 0, t20 = 0, t21 = 0;
            if (m < p.M) {
                const float* vwp = p.vw + (size_t)3 * m * 256;
#pragma unroll
                for (int ii = 0; ii < 8; ii++) {
                    int o = lane + 32 * ii;
                    float ga = st[(size_t)ml * SROW + o];
                    float w0 = sW[2 * o], w1 = sW[2 * o + 1];
                    float q0 = ga * vwp[o];
                    float q1 = ga * vwp[256 + o];
                    float q2 = ga * vwp[512 + o];
                    t00 += q0 * w0; t01 += q0 * w1;
                    t10 += q1 * w0; t11 += q1 * w1;
                    t20 += q2 * w0; t21 += q2 * w1;
                }
            }
#pragma unroll
            for (int off = 16; off; off >>= 1) {
                t00 += __shfl_xor_sync(0xffffffffu, t00, off);
                t01 += __shfl_xor_sync(0xffffffffu, t01, off);
                t10 += __shfl_xor_sync(0xffffffffu, t10, off);
                t11 += __shfl_xor_sync(0xffffffffu, t11, off);
                t20 += __shfl_xor_sync(0xffffffffu, t20, off);
                t21 += __shfl_xor_sync(0xffffffffu, t21, off);
            }
            if (lane == 0 && m < p.M) {
                p.vvn2[m] = sqrtf(t00 * t00 + t10 * t10 + t20 * t20);
                p.vw2[3 * m + 0] = t01;
                p.vw2[3 * m + 1] = t11;
                p.vw2[3 * m + 2] = t21;
            }
        }
        return;
    }

    if (EPI == 3) {
        // h2 tile -> smem, then fused stage2b (final matvec + segment sums).
#pragma unroll
        for (int i = 0; i < 4; i++)
#pragma unroll
            for (int half = 0; half < 2; half++) {
                const int ml = wm * 64 + i * 16 + mrow + half * 8;
                const int m  = row0 + ml;
                float um = (m < p.M) ? p.u[m] : 0.f;
#pragma unroll
                for (int j = 0; j < 8; j++) {
                    const int nl = wn * 64 + j * 8 + ncol;
                    float v0 = silu_f(acc[i][j][half * 2] +
                                      um * p.vrow[nl] + p.bias[nl]);
                    float v1 = silu_f(acc[i][j][half * 2 + 1] +
                                      um * p.vrow[nl + 1] + p.bias[nl + 1]);
                    *(float2*)(st + (size_t)ml * SROW + nl) = make_float2(v0, v1);
                }
            }
        sW[tid] = p.W2b[tid];
        sW[256 + tid] = p.W2b[256 + tid];
        if (tid == 0) { sW[512] = p.b2b[0]; sW[513] = p.b2b[1]; }
        __syncthreads();
#pragma unroll 1
        for (int t = 0; t < 16; t++) {
            const int ml = wid * 16 + t;
            const int m  = row0 + ml;
            float x0 = 0, x1 = 0;
            if (m < p.M) {
#pragma unroll
                for (int ii = 0; ii < 8; ii++) {
                    int k = lane + 32 * ii;
                    float hv = st[(size_t)ml * SROW + k];
                    x0 += hv * sW[2 * k];
                    x1 += hv * sW[2 * k + 1];
                }
            }
#pragma unroll
            for (int off = 16; off; off >>= 1) {
                x0 += __shfl_xor_sync(0xffffffffu, x0, off);
                x1 += __shfl_xor_sync(0xffffffffu, x1, off);
            }
            if (lane == 0 && m < p.M) {
                float charge = x0 + sW[512];
                float gate2  = x1 + sW[513];
                int b = p.batch[m];
#pragma unroll
                for (int c = 0; c < 3; c++) {
                    float v2 = gate2 * p.vw2[3 * m + c];
                    float y  = v2 + p.pos[3 * m + c] * charge;
                    atomicAdd(&p.out[(size_t)b * 3 + c], y);
                    atomicAdd(&p.out[(size_t)p.nmol * 3 + (size_t)b * 3 + c], v2);
                }
            }
        }
        return;
    }

    // Generic register epilogues (EPI 0 col 256, EPI 1, EPI 2 col 0)
#pragma unroll
    for (int i = 0; i < 4; i++) {
        const int mbase = row0 + wm * 64 + i * 16 + mrow;
#pragma unroll
        for (int half = 0; half < 2; half++) {
            const int m = mbase + half * 8;
            if (m >= p.M) continue;
#pragma unroll
            for (int j = 0; j < 8; j++) {
                const int n = col0 + wn * 64 + j * 8 + ncol;
                float v0 = acc[i][j][half * 2 + 0];
                float v1 = acc[i][j][half * 2 + 1];
                if (EPI == 0) {
                    // GEMM1 vW tile: fp32 -> C0 (ld 256)
                    *(float2*)(p.C0 + (size_t)m * 256 + (n - 256)) = make_float2(v0, v1);
                } else {
                    // EPI 1, or EPI 2 col 0: silu(v+bias) -> fp16 hi/lo
                    v0 = silu_f(v0 + p.bias[n]);
                    v1 = silu_f(v1 + p.bias[n + 1]);
                    __half h0, l0, h1, l1;
                    split_f16(v0, h0, l0);
                    split_f16(v1, h1, l1);
                    *(__half2*)(p.Oh + (size_t)m * 256 + n) = __half2(h0, h1);
                    *(__half2*)(p.Ol + (size_t)m * 256 + n) = __half2(l0, l1);
                }
            }
        }
    }
}

// ---------------------------------------------------------------------------
// weights: W [K,N] fp32 -> transposed fp16 [N,K]
// ---------------------------------------------------------------------------
__global__ void wt_conv(const float* __restrict__ W,
                        __half* __restrict__ t, int K, int N) {
    int idx = blockIdx.x * blockDim.x + threadIdx.x;
    if (idx >= K * N) return;
    int k = idx / N, n = idx % N;
    t[(size_t)n * K + k] = __float2half_rn(W[idx]);
}

// ---------------------------------------------------------------------------
extern "C" void kernel_launch(void* const* d_in, const int* in_sizes, int n_in,
                              void* d_out, int out_size) {
    const float* pos   = (const float*)d_in[0];
    const float* l0    = (const float*)d_in[1];
    const float* l1    = (const float*)d_in[2];
    const int*   batch = (const int*)d_in[3];
    const float* Wmix1 = (const float*)d_in[4];
    const float* W1a   = (const float*)d_in[5];
    const float* b1a   = (const float*)d_in[6];
    const float* W2a   = (const float*)d_in[7];
    const float* b2a   = (const float*)d_in[8];
    const float* Wmix2 = (const float*)d_in[9];
    const float* W1b   = (const float*)d_in[10];
    const float* b1b   = (const float*)d_in[11];
    const float* W2b   = (const float*)d_in[12];
    const float* b2b   = (const float*)d_in[13];

    const int natoms = in_sizes[3];
    const int nmol   = out_size / 6;
    float* out = (float*)d_out;

    float *vw, *vvn2, *vw2;
    __half *a2h, *a2l, *a3h, *a3l, *a4h, *a4l;
    __half *bt1, *bt2, *bt3, *bt4;
    cudaGetSymbolAddress((void**)&vw,   g_vw);
    cudaGetSymbolAddress((void**)&vvn2, g_vvn2);
    cudaGetSymbolAddress((void**)&vw2,  g_vw2);
    cudaGetSymbolAddress((void**)&a2h, g_a2h);  cudaGetSymbolAddress((void**)&a2l, g_a2l);
    cudaGetSymbolAddress((void**)&a3h, g_a3h);  cudaGetSymbolAddress((void**)&a3l, g_a3l);
    cudaGetSymbolAddress((void**)&a4h, g_a4h);  cudaGetSymbolAddress((void**)&a4l, g_a4l);
    cudaGetSymbolAddress((void**)&bt1, g_bt1);
    cudaGetSymbolAddress((void**)&bt2, g_bt2);
    cudaGetSymbolAddress((void**)&bt3, g_bt3);
    cudaGetSymbolAddress((void**)&bt4, g_bt4);

    cudaFuncSetAttribute(gemm_mma<0>, cudaFuncAttributeMaxDynamicSharedMemorySize, SMEM_DYN);
    cudaFuncSetAttribute(gemm_mma<1>, cudaFuncAttributeMaxDynamicSharedMemorySize, SMEM_DYN);
    cudaFuncSetAttribute(gemm_mma<2>, cudaFuncAttributeMaxDynamicSharedMemorySize, SMEM_DYN);
    cudaFuncSetAttribute(gemm_mma<3>, cudaFuncAttributeMaxDynamicSharedMemorySize, SMEM_DYN);

    cudaMemsetAsync(d_out, 0, (size_t)out_size * sizeof(float));

    const int M1  = 3 * natoms;
    const int mt1 = (M1 + 125) / 126;          // GEMM1: 126-row tiles (42 atoms)
    const int mt  = (natoms + 127) / 128;

    // weight transposes (single fp16)
    wt_conv<<<(256 * 512 + 255) / 256, 256>>>(Wmix1, bt1, 256, 512);
    wt_conv<<<(512 * 256 + 255) / 256, 256>>>(W1a,   bt2, 512, 256);
    wt_conv<<<(256 * 512 + 255) / 256, 256>>>(W2a,   bt3, 256, 512);
    wt_conv<<<(256 * 256 + 255) / 256, 256>>>(W1b,   bt4, 256, 256);

    // GEMM1: vmix = l1 @ Wmix1 (3N x 512), A loaded fp32 + split in-kernel.
    // col tile 0 -> fused vVn norms into a2 cols 256:512; col tile 1 -> vW.
    {
        MP p = {};
        p.Af = l1; p.ldaf = 256; p.ksplit = 256;
        p.Ah = a2h; p.Al = a2l; p.ldah = 512; p.coffh = 0;   // unused
        p.B = bt1; p.M = M1; p.K = 256; p.mstep = 126;
        p.C0 = vw; p.Oh = a2h; p.Ol = a2l;
        gemm_mma<0><<<dim3(2, mt1), 256, SMEM_DYN>>>(p);
    }

    // GEMM2: h = silu([l0 | vVn] @ W1a + b1a) -> a3 (hi/lo).
    // k<256 from l0 fp32 (in-kernel split); k>=256 from a2 fp16 (norms).
    {
        MP p = {};
        p.Af = l0; p.ldaf = 256; p.ksplit = 256;
        p.Ah = a2h; p.Al = a2l; p.ldah = 512; p.coffh = 256;
        p.B = bt2; p.M = natoms; p.K = 512; p.mstep = 128;
        p.Oh = a3h; p.Ol = a3l; p.bias = b1a;
        gemm_mma<1><<<dim3(1, mt), 256, SMEM_DYN>>>(p);
    }

    // GEMM3: x = h @ W2a + b2a. col tile 0: s1 = silu -> a4 hi/lo;
    // col tile 1: gate -> fused stage2a (vvn2, vw2).
    {
        MP p = {};
        p.Af = nullptr; p.ldaf = 256; p.ksplit = 0;
        p.Ah = a3h; p.Al = a3l; p.ldah = 256; p.coffh = 0;
        p.B = bt3; p.M = natoms; p.K = 256; p.mstep = 128;
        p.Oh = a4h; p.Ol = a4l; p.bias = b2a;
        p.vw = vw; p.Wmix2 = Wmix2; p.vvn2 = vvn2; p.vw2 = vw2;
        gemm_mma<2><<<dim3(2, mt), 256, SMEM_DYN>>>(p);
    }

    // GEMM4: h2 = silu(s1 @ W1b[:256] + vvn2*W1b[256] + b1b) -> fused
    // stage2b: charge/gate2 matvec + gating + segment atomics.
    {
        MP p = {};
        p.Af = nullptr; p.ldaf = 256; p.ksplit = 0;
        p.Ah = a4h; p.Al = a4l; p.ldah = 256; p.coffh = 0;
        p.B = bt4; p.M = natoms; p.K = 256; p.mstep = 128;
        p.bias = b1b; p.u = vvn2; p.vrow = W1b + 256 * 256;
        p.W2b = W2b; p.b2b = b2b; p.pos = pos; p.batch = batch;
        p.vw2 = vw2; p.out = out; p.nmol = nmol;
        gemm_mma<3><<<dim3(1, mt), 256, SMEM_DYN>>>(p);
    }
}

// round 7
// speedup vs baseline: 3.3616x; 1.0043x over previous
#include <cuda_runtime.h>
#include <cuda_fp16.h>
#include <cstdint>
#include <cstddef>

// ---------------------------------------------------------------------------
// Dipole head: asymmetric fp16 2-pass GEMMs on mma.sync (HMMA), fp32 accum.
// R6: fp32->fp16 split fused into GEMM loaders (act_conv gone), stage2a fused
//     into GEMM3 epilogue, stage2b fused into GEMM4 epilogue, 1 barrier/chunk.
// GEMM arithmetic identical to R5 (rel_err must stay ~6.4e-4).
// ---------------------------------------------------------------------------

#define NA_MAX 200000
#define MPAD   200128   // padded rows for per-atom fp16 activation buffers

// ---------------- global scratch (zero-initialized at module load) ----------
__device__ __align__(128) float g_vw[(size_t)3 * NA_MAX * 256];   // vW fp32
__device__ __align__(128) __half g_a2h[(size_t)MPAD * 512];
__device__ __align__(128) __half g_a2l[(size_t)MPAD * 512];
__device__ __align__(128) __half g_a3h[(size_t)MPAD * 256];
__device__ __align__(128) __half g_a3l[(size_t)MPAD * 256];
__device__ __align__(128) __half g_a4h[(size_t)MPAD * 256];
__device__ __align__(128) __half g_a4l[(size_t)MPAD * 256];
__device__ float g_vvn2[NA_MAX];
__device__ float g_vw2[3 * NA_MAX];
__device__ __align__(128) __half g_bt1[512 * 256];
__device__ __align__(128) __half g_bt2[256 * 512];
__device__ __align__(128) __half g_bt3[512 * 256];
__device__ __align__(128) __half g_bt4[256 * 256];

// ---------------- helpers ----------------------------------------------
__device__ __forceinline__ uint32_t smem_u32(const void* p) {
    uint32_t a;
    asm("{ .reg .u64 t; cvta.to.shared.u64 t, %1; cvt.u32.u64 %0, t; }"
        : "=r"(a) : "l"(p));
    return a;
}
#define SWZ128(off) ((off) ^ (((off) >> 3) & 0x70))

__device__ __forceinline__ void cp16(uint32_t saddr, const void* gaddr) {
    asm volatile("cp.async.cg.shared.global [%0], [%1], 16;\n"
                 :: "r"(saddr), "l"(gaddr));
}
__device__ __forceinline__ void cp_commit() {
    asm volatile("cp.async.commit_group;\n" ::: "memory");
}

__device__ __forceinline__ void ldsm_x4(uint32_t* r, uint32_t a) {
    asm volatile("ldmatrix.sync.aligned.m8n8.x4.shared.b16 {%0,%1,%2,%3}, [%4];"
                 : "=r"(r[0]), "=r"(r[1]), "=r"(r[2]), "=r"(r[3]) : "r"(a));
}

__device__ __forceinline__ void mma16816(float* d, const uint32_t* a,
                                         const uint32_t* b) {
    asm volatile(
        "mma.sync.aligned.m16n8k16.row.col.f32.f16.f16.f32 "
        "{%0,%1,%2,%3}, {%4,%5,%6,%7}, {%8,%9}, {%0,%1,%2,%3};\n"
        : "+f"(d[0]), "+f"(d[1]), "+f"(d[2]), "+f"(d[3])
        : "r"(a[0]), "r"(a[1]), "r"(a[2]), "r"(a[3]), "r"(b[0]), "r"(b[1]));
}

__device__ __forceinline__ float silu_f(float x) { return x / (1.0f + __expf(-x)); }

__device__ __forceinline__ void split_f16(float v, __half& h, __half& l) {
    h = __float2half_rn(v);
    l = __float2half_rn(v - __half2float(h));
}

// ---------------------------------------------------------------------------
// HMMA GEMM, CTA tile 128x256, warp tile 64x64 (8 warps), K-chunk 64,
// 2-stage ring with in-loader fp32->fp16 hi/lo conversion for k < ksplit.
// EPI 0: GEMM1 — col0==0: vector norms -> Oh/Ol cols 256:512;
//        col0==256: vW fp32 -> C0 (ld 256)
// EPI 1: silu(v+bias) -> fp16 hi/lo (ld 256)
// EPI 2: col0==0: silu(v+bias)->hi/lo ; col0==256: gate=v+bias -> fused
//        stage2a (vvn2, vw2)
// EPI 3: h2 = silu(v + u[m]*vrow[n] + bias) -> fused stage2b (segment sums)
// ---------------------------------------------------------------------------
struct MP {
    const float*  Af;        // fp32 A source for k < ksplit
    int           ldaf;
    const __half *Ah, *Al;   // fp16 A source for k >= ksplit
    int           ldah, coffh;
    const __half *B;
    int M, K, ksplit, mstep;
    float *C0;
    __half *Oh, *Ol;
    const float *bias, *u, *vrow;
    // fused stage2a (EPI 2):
    const float *vw, *Wmix2;
    float *vvn2, *vw2;
    // fused stage2b (EPI 3):
    const float *W2b, *b2b, *pos;
    const int *batch;
    float *out;
    int nmol;
};

#define OFF_AL  16384
#define OFF_B   32768
#define OFF_F32 65536
#define STG     98304
#define SMEM_DYN (2 * STG)
#define SROW 264   // fp32 smem tile row stride (fused epilogues)

template <int EPI>
__global__ void __launch_bounds__(256, 1) gemm_mma(const MP p) {
    extern __shared__ __align__(1024) char smem[];
    const uint32_t sb = smem_u32(smem);
    const int tid  = threadIdx.x;
    const int wid  = tid >> 5;
    const int lane = tid & 31;
    const int wm   = wid >> 2;   // 0..1  (64-row slab)
    const int wn   = wid & 3;    // 0..3  (64-col slab)
    const int row0 = blockIdx.y * p.mstep;
    const int col0 = blockIdx.x * 256;

    // ldmatrix per-lane address components
    const int      rA0 = wm * 64 + (lane & 7) + ((lane >> 3) & 1) * 8;
    const uint32_t xA  = (uint32_t)(rA0 & 7) << 4;
    const uint32_t kA  = (uint32_t)(lane >> 4) * 16;
    const int      rB0 = wn * 64 + ((lane >> 4) * 8) + (lane & 7);
    const uint32_t xB  = (uint32_t)(rB0 & 7) << 4;
    const uint32_t kB  = (uint32_t)((lane >> 3) & 1) * 16;

    float acc[4][8][4];
#pragma unroll
    for (int i = 0; i < 4; i++)
#pragma unroll
        for (int j = 0; j < 8; j++)
#pragma unroll
            for (int q = 0; q < 4; q++) acc[i][j][q] = 0.f;

    const int NC = p.K >> 6;   // 64-wide K chunks

    auto load_chunk = [&](int kc, int s) {
        const uint32_t base = sb + s * STG;
        const int koff = kc * 64;
        if (koff < p.ksplit) {
            // fp32 A chunk -> staging buffer (linear, 256 B/row)
#pragma unroll
            for (int i = 0; i < 8; i++) {
                int idx = i * 256 + tid;
                int r = idx >> 4, u = idx & 15;
                int gr = row0 + r;
                if (gr > p.M - 1) gr = p.M - 1;
                cp16(base + OFF_F32 + (uint32_t)(r * 256 + u * 16),
                     p.Af + (size_t)gr * p.ldaf + koff + u * 4);
            }
        } else {
            // fp16 hi/lo A chunk -> swizzled tiles
#pragma unroll
            for (int i = 0; i < 4; i++) {
                int idx = i * 256 + tid;
                int r = idx >> 3, ch = idx & 7;
                uint32_t so = SWZ128((uint32_t)(r * 128 + ch * 16));
                int gr = row0 + r;
                if (gr > p.M - 1) gr = p.M - 1;
                size_t ga = (size_t)gr * p.ldah + p.coffh + (koff - p.ksplit) + ch * 8;
                cp16(base + so,          p.Ah + ga);
                cp16(base + OFF_AL + so, p.Al + ga);
            }
        }
#pragma unroll
        for (int i = 0; i < 8; i++) {
            int idx = i * 256 + tid;
            int r = idx >> 3, ch = idx & 7;
            uint32_t so = SWZ128((uint32_t)(r * 128 + ch * 16));
            size_t gb = (size_t)(col0 + r) * p.K + koff + ch * 8;
            cp16(base + OFF_B + so, p.B + gb);
        }
        cp_commit();
    };

    auto convert_stage = [&](int s) {
        char* stg = smem + s * STG;
#pragma unroll
        for (int i = 0; i < 4; i++) {
            int idx = i * 256 + tid;
            int r = idx >> 3, ch = idx & 7;
            const float* src = (const float*)(stg + OFF_F32 + r * 256 + ch * 32);
            float4 a = *(const float4*)(src);
            float4 b = *(const float4*)(src + 4);
            float f[8] = {a.x, a.y, a.z, a.w, b.x, b.y, b.z, b.w};
            __half hh[8], ll[8];
#pragma unroll
            for (int q = 0; q < 8; q++) split_f16(f[q], hh[q], ll[q]);
            uint32_t so = SWZ128((uint32_t)(r * 128 + ch * 16));
            *(uint4*)(stg + so)          = *(const uint4*)hh;
            *(uint4*)(stg + OFF_AL + so) = *(const uint4*)ll;
        }
    };

    load_chunk(0, 0);

    for (int c = 0; c < NC; c++) {
        const int s = c & 1;
        asm volatile("cp.async.wait_group 0;\n" ::: "memory");
        __syncthreads();
        if (c + 1 < NC) load_chunk(c + 1, s ^ 1);
        if ((c << 6) < p.ksplit) {
            convert_stage(s);
            __syncthreads();
        }

        const uint32_t base = sb + s * STG;
#pragma unroll
        for (int ks = 0; ks < 4; ks++) {
            const uint32_t kbA = ((uint32_t)(ks * 32) + kA) ^ xA;
            const uint32_t kbB = ((uint32_t)(ks * 32) + kB) ^ xB;
            uint32_t Ah4[4][4], Al4[4][4];
#pragma unroll
            for (int i = 0; i < 4; i++) {
                uint32_t ro = (uint32_t)(rA0 + i * 16) * 128;
                ldsm_x4(Ah4[i], base + ro + kbA);
                ldsm_x4(Al4[i], base + OFF_AL + ro + kbA);
            }
#pragma unroll
            for (int jp = 0; jp < 4; jp++) {
                uint32_t ro = (uint32_t)(rB0 + jp * 16) * 128;
                uint32_t bb[4];
                ldsm_x4(bb, base + OFF_B + ro + kbB);
#pragma unroll
                for (int i = 0; i < 4; i++) {
                    mma16816(acc[i][2 * jp],     Ah4[i], bb);
                    mma16816(acc[i][2 * jp + 1], Ah4[i], bb + 2);
                    mma16816(acc[i][2 * jp],     Al4[i], bb);
                    mma16816(acc[i][2 * jp + 1], Al4[i], bb + 2);
                }
            }
        }
    }
    __syncthreads();   // retire smem tiles before epilogue reuse

    // ---------------- epilogue ----------------
    const int mrow = lane >> 2;          // 0..7
    const int ncol = (lane & 3) * 2;     // 0,2,4,6
    float* st = (float*)smem;
    float* sW = st + 128 * SROW;

    if (EPI == 0 && col0 == 0) {
        // GEMM1 vV tile: stage accumulators, compute per-atom norms.
#pragma unroll
        for (int i = 0; i < 4; i++)
#pragma unroll
            for (int half = 0; half < 2; half++) {
                const int ml = wm * 64 + i * 16 + mrow + half * 8;
#pragma unroll
                for (int j = 0; j < 8; j++) {
                    const int nl = wn * 64 + j * 8 + ncol;
                    *(float2*)(st + (size_t)ml * SROW + nl) =
                        make_float2(acc[i][j][half * 2], acc[i][j][half * 2 + 1]);
                }
            }
        __syncthreads();
        const int atom0 = row0 / 3;
#pragma unroll 2
        for (int it = 0; it < 42; it++) {
            int idx = it * 256 + tid;
            int ai = idx >> 8, o = idx & 255;
            int a = atom0 + ai;
            if (3 * a + 2 < p.M) {
                float x = st[(size_t)(3 * ai)     * SROW + o];
                float y = st[(size_t)(3 * ai + 1) * SROW + o];
                float z = st[(size_t)(3 * ai + 2) * SROW + o];
                float v = sqrtf(x * x + y * y + z * z);
                __half h, l;
                split_f16(v, h, l);
                p.Oh[(size_t)a * 512 + 256 + o] = h;
                p.Ol[(size_t)a * 512 + 256 + o] = l;
            }
        }
        return;
    }

    if (EPI == 2 && col0 == 256) {
        // gate tile -> smem, then fused stage2a.
#pragma unroll
        for (int i = 0; i < 4; i++)
#pragma unroll
            for (int half = 0; half < 2; half++) {
                const int ml = wm * 64 + i * 16 + mrow + half * 8;
#pragma unroll
                for (int j = 0; j < 8; j++) {
                    const int nl = wn * 64 + j * 8 + ncol;
                    float v0 = acc[i][j][half * 2]     + p.bias[256 + nl];
                    float v1 = acc[i][j][half * 2 + 1] + p.bias[256 + nl + 1];
                    *(float2*)(st + (size_t)ml * SROW + nl) = make_float2(v0, v1);
                }
            }
        sW[tid] = p.Wmix2[tid];
        sW[256 + tid] = p.Wmix2[256 + tid];
        __syncthreads();
#pragma unroll 1
        for (int t = 0; t < 16; t++) {
            const int ml = wid * 16 + t;
            const int m  = row0 + ml;
            float t00 = 0, t01 = 0, t10 = 0, t11 = 0, t20 = 0, t21 = 0;
            if (m < p.M) {
                const float* vwp = p.vw + (size_t)3 * m * 256;
#pragma unroll
                for (int ii = 0; ii < 8; ii++) {
                    int o = lane + 32 * ii;
                    float ga = st[(size_t)ml * SROW + o];
                    float w0 = sW[2 * o], w1 = sW[2 * o + 1];
                    float q0 = ga * vwp[o];
                    float q1 = ga * vwp[256 + o];
                    float q2 = ga * vwp[512 + o];
                    t00 += q0 * w0; t01 += q0 * w1;
                    t10 += q1 * w0; t11 += q1 * w1;
                    t20 += q2 * w0; t21 += q2 * w1;
                }
            }
#pragma unroll
            for (int off = 16; off; off >>= 1) {
                t00 += __shfl_xor_sync(0xffffffffu, t00, off);
                t01 += __shfl_xor_sync(0xffffffffu, t01, off);
                t10 += __shfl_xor_sync(0xffffffffu, t10, off);
                t11 += __shfl_xor_sync(0xffffffffu, t11, off);
                t20 += __shfl_xor_sync(0xffffffffu, t20, off);
                t21 += __shfl_xor_sync(0xffffffffu, t21, off);
            }
            if (lane == 0 && m < p.M) {
                p.vvn2[m] = sqrtf(t00 * t00 + t10 * t10 + t20 * t20);
                p.vw2[3 * m + 0] = t01;
                p.vw2[3 * m + 1] = t11;
                p.vw2[3 * m + 2] = t21;
            }
        }
        return;
    }

    if (EPI == 3) {
        // h2 tile -> smem, then fused stage2b (final matvec + segment sums).
#pragma unroll
        for (int i = 0; i < 4; i++)
#pragma unroll
            for (int half = 0; half < 2; half++) {
                const int ml = wm * 64 + i * 16 + mrow + half * 8;
                const int m  = row0 + ml;
                float um = (m < p.M) ? p.u[m] : 0.f;
#pragma unroll
                for (int j = 0; j < 8; j++) {
                    const int nl = wn * 64 + j * 8 + ncol;
                    float v0 = silu_f(acc[i][j][half * 2] +
                                      um * p.vrow[nl] + p.bias[nl]);
                    float v1 = silu_f(acc[i][j][half * 2 + 1] +
                                      um * p.vrow[nl + 1] + p.bias[nl + 1]);
                    *(float2*)(st + (size_t)ml * SROW + nl) = make_float2(v0, v1);
                }
            }
        sW[tid] = p.W2b[tid];
        sW[256 + tid] = p.W2b[256 + tid];
        if (tid == 0) { sW[512] = p.b2b[0]; sW[513] = p.b2b[1]; }
        __syncthreads();
#pragma unroll 1
        for (int t = 0; t < 16; t++) {
            const int ml = wid * 16 + t;
            const int m  = row0 + ml;
            float x0 = 0, x1 = 0;
            if (m < p.M) {
#pragma unroll
                for (int ii = 0; ii < 8; ii++) {
                    int k = lane + 32 * ii;
                    float hv = st[(size_t)ml * SROW + k];
                    x0 += hv * sW[2 * k];
                    x1 += hv * sW[2 * k + 1];
                }
            }
#pragma unroll
            for (int off = 16; off; off >>= 1) {
                x0 += __shfl_xor_sync(0xffffffffu, x0, off);
                x1 += __shfl_xor_sync(0xffffffffu, x1, off);
            }
            if (lane == 0 && m < p.M) {
                float charge = x0 + sW[512];
                float gate2  = x1 + sW[513];
                int b = p.batch[m];
#pragma unroll
                for (int c = 0; c < 3; c++) {
                    float v2 = gate2 * p.vw2[3 * m + c];
                    float y  = v2 + p.pos[3 * m + c] * charge;
                    atomicAdd(&p.out[(size_t)b * 3 + c], y);
                    atomicAdd(&p.out[(size_t)p.nmol * 3 + (size_t)b * 3 + c], v2);
                }
            }
        }
        return;
    }

    // Generic register epilogues (EPI 0 col 256, EPI 1, EPI 2 col 0)
#pragma unroll
    for (int i = 0; i < 4; i++) {
        const int mbase = row0 + wm * 64 + i * 16 + mrow;
#pragma unroll
        for (int half = 0; half < 2; half++) {
            const int m = mbase + half * 8;
            if (m >= p.M) continue;
#pragma unroll
            for (int j = 0; j < 8; j++) {
                const int n = col0 + wn * 64 + j * 8 + ncol;
                float v0 = acc[i][j][half * 2 + 0];
                float v1 = acc[i][j][half * 2 + 1];
                if (EPI == 0) {
                    // GEMM1 vW tile: fp32 -> C0 (ld 256)
                    *(float2*)(p.C0 + (size_t)m * 256 + (n - 256)) = make_float2(v0, v1);
                } else {
                    // EPI 1, or EPI 2 col 0: silu(v+bias) -> fp16 hi/lo
                    v0 = silu_f(v0 + p.bias[n]);
                    v1 = silu_f(v1 + p.bias[n + 1]);
                    __half h0, l0, h1, l1;
                    split_f16(v0, h0, l0);
                    split_f16(v1, h1, l1);
                    *(__half2*)(p.Oh + (size_t)m * 256 + n) = __half2(h0, h1);
                    *(__half2*)(p.Ol + (size_t)m * 256 + n) = __half2(l0, l1);
                }
            }
        }
    }
}

// ---------------------------------------------------------------------------
// weights: W [K,N] fp32 -> transposed fp16 [N,K]
// ---------------------------------------------------------------------------
__global__ void wt_conv(const float* __restrict__ W,
                        __half* __restrict__ t, int K, int N) {
    int idx = blockIdx.x * blockDim.x + threadIdx.x;
    if (idx >= K * N) return;
    int k = idx / N, n = idx % N;
    t[(size_t)n * K + k] = __float2half_rn(W[idx]);
}

// ---------------------------------------------------------------------------
extern "C" void kernel_launch(void* const* d_in, const int* in_sizes, int n_in,
                              void* d_out, int out_size) {
    const float* pos   = (const float*)d_in[0];
    const float* l0    = (const float*)d_in[1];
    const float* l1    = (const float*)d_in[2];
    const int*   batch = (const int*)d_in[3];
    const float* Wmix1 = (const float*)d_in[4];
    const float* W1a   = (const float*)d_in[5];
    const float* b1a   = (const float*)d_in[6];
    const float* W2a   = (const float*)d_in[7];
    const float* b2a   = (const float*)d_in[8];
    const float* Wmix2 = (const float*)d_in[9];
    const float* W1b   = (const float*)d_in[10];
    const float* b1b   = (const float*)d_in[11];
    const float* W2b   = (const float*)d_in[12];
    const float* b2b   = (const float*)d_in[13];

    const int natoms = in_sizes[3];
    const int nmol   = out_size / 6;
    float* out = (float*)d_out;

    float *vw, *vvn2, *vw2;
    __half *a2h, *a2l, *a3h, *a3l, *a4h, *a4l;
    __half *bt1, *bt2, *bt3, *bt4;
    cudaGetSymbolAddress((void**)&vw,   g_vw);
    cudaGetSymbolAddress((void**)&vvn2, g_vvn2);
    cudaGetSymbolAddress((void**)&vw2,  g_vw2);
    cudaGetSymbolAddress((void**)&a2h, g_a2h);  cudaGetSymbolAddress((void**)&a2l, g_a2l);
    cudaGetSymbolAddress((void**)&a3h, g_a3h);  cudaGetSymbolAddress((void**)&a3l, g_a3l);
    cudaGetSymbolAddress((void**)&a4h, g_a4h);  cudaGetSymbolAddress((void**)&a4l, g_a4l);
    cudaGetSymbolAddress((void**)&bt1, g_bt1);
    cudaGetSymbolAddress((void**)&bt2, g_bt2);
    cudaGetSymbolAddress((void**)&bt3, g_bt3);
    cudaGetSymbolAddress((void**)&bt4, g_bt4);

    cudaFuncSetAttribute(gemm_mma<0>, cudaFuncAttributeMaxDynamicSharedMemorySize, SMEM_DYN);
    cudaFuncSetAttribute(gemm_mma<1>, cudaFuncAttributeMaxDynamicSharedMemorySize, SMEM_DYN);
    cudaFuncSetAttribute(gemm_mma<2>, cudaFuncAttributeMaxDynamicSharedMemorySize, SMEM_DYN);
    cudaFuncSetAttribute(gemm_mma<3>, cudaFuncAttributeMaxDynamicSharedMemorySize, SMEM_DYN);

    cudaMemsetAsync(d_out, 0, (size_t)out_size * sizeof(float));

    const int M1  = 3 * natoms;
    const int mt1 = (M1 + 125) / 126;          // GEMM1: 126-row tiles (42 atoms)
    const int mt  = (natoms + 127) / 128;

    // weight transposes (single fp16)
    wt_conv<<<(256 * 512 + 255) / 256, 256>>>(Wmix1, bt1, 256, 512);
    wt_conv<<<(512 * 256 + 255) / 256, 256>>>(W1a,   bt2, 512, 256);
    wt_conv<<<(256 * 512 + 255) / 256, 256>>>(W2a,   bt3, 256, 512);
    wt_conv<<<(256 * 256 + 255) / 256, 256>>>(W1b,   bt4, 256, 256);

    // GEMM1: vmix = l1 @ Wmix1 (3N x 512), A loaded fp32 + split in-kernel.
    // col tile 0 -> fused vVn norms into a2 cols 256:512; col tile 1 -> vW.
    {
        MP p = {};
        p.Af = l1; p.ldaf = 256; p.ksplit = 256;
        p.Ah = a2h; p.Al = a2l; p.ldah = 512; p.coffh = 0;   // unused
        p.B = bt1; p.M = M1; p.K = 256; p.mstep = 126;
        p.C0 = vw; p.Oh = a2h; p.Ol = a2l;
        gemm_mma<0><<<dim3(2, mt1), 256, SMEM_DYN>>>(p);
    }

    // GEMM2: h = silu([l0 | vVn] @ W1a + b1a) -> a3 (hi/lo).
    // k<256 from l0 fp32 (in-kernel split); k>=256 from a2 fp16 (norms).
    {
        MP p = {};
        p.Af = l0; p.ldaf = 256; p.ksplit = 256;
        p.Ah = a2h; p.Al = a2l; p.ldah = 512; p.coffh = 256;
        p.B = bt2; p.M = natoms; p.K = 512; p.mstep = 128;
        p.Oh = a3h; p.Ol = a3l; p.bias = b1a;
        gemm_mma<1><<<dim3(1, mt), 256, SMEM_DYN>>>(p);
    }

    // GEMM3: x = h @ W2a + b2a. col tile 0: s1 = silu -> a4 hi/lo;
    // col tile 1: gate -> fused stage2a (vvn2, vw2).
    {
        MP p = {};
        p.Af = nullptr; p.ldaf = 256; p.ksplit = 0;
        p.Ah = a3h; p.Al = a3l; p.ldah = 256; p.coffh = 0;
        p.B = bt3; p.M = natoms; p.K = 256; p.mstep = 128;
        p.Oh = a4h; p.Ol = a4l; p.bias = b2a;
        p.vw = vw; p.Wmix2 = Wmix2; p.vvn2 = vvn2; p.vw2 = vw2;
        gemm_mma<2><<<dim3(2, mt), 256, SMEM_DYN>>>(p);
    }

    // GEMM4: h2 = silu(s1 @ W1b[:256] + vvn2*W1b[256] + b1b) -> fused
    // stage2b: charge/gate2 matvec + gating + segment atomics.
    {
        MP p = {};
        p.Af = nullptr; p.ldaf = 256; p.ksplit = 0;
        p.Ah = a4h; p.Al = a4l; p.ldah = 256; p.coffh = 0;
        p.B = bt4; p.M = natoms; p.K = 256; p.mstep = 128;
        p.bias = b1b; p.u = vvn2; p.vrow = W1b + 256 * 256;
        p.W2b = W2b; p.b2b = b2b; p.pos = pos; p.batch = batch;
        p.vw2 = vw2; p.out = out; p.nmol = nmol;
        gemm_mma<3><<<dim3(1, mt), 256, SMEM_DYN>>>(p);
    }
}

// round 8
// speedup vs baseline: 3.7946x; 1.1288x over previous
#include <cuda_runtime.h>
#include <cuda_fp16.h>
#include <cstdint>
#include <cstddef>

// ---------------------------------------------------------------------------
// Dipole head: asymmetric fp16 2-pass GEMMs on mma.sync (HMMA), fp32 accum.
// R7: 512 threads / 16 warps per CTA (warp tile 32x64) for 4 warps/SMSP
//     latency hiding; same 128x256 CTA tile, same math -> same rel_err.
// ---------------------------------------------------------------------------

#define NA_MAX 200000
#define MPAD   200128   // padded rows for per-atom fp16 activation buffers

// ---------------- global scratch (zero-initialized at module load) ----------
__device__ __align__(128) float g_vw[(size_t)3 * NA_MAX * 256];   // vW fp32
__device__ __align__(128) __half g_a2h[(size_t)MPAD * 512];
__device__ __align__(128) __half g_a2l[(size_t)MPAD * 512];
__device__ __align__(128) __half g_a3h[(size_t)MPAD * 256];
__device__ __align__(128) __half g_a3l[(size_t)MPAD * 256];
__device__ __align__(128) __half g_a4h[(size_t)MPAD * 256];
__device__ __align__(128) __half g_a4l[(size_t)MPAD * 256];
__device__ float g_vvn2[NA_MAX];
__device__ float g_vw2[3 * NA_MAX];
__device__ __align__(128) __half g_bt1[512 * 256];
__device__ __align__(128) __half g_bt2[256 * 512];
__device__ __align__(128) __half g_bt3[512 * 256];
__device__ __align__(128) __half g_bt4[256 * 256];

// ---------------- helpers ----------------------------------------------
__device__ __forceinline__ uint32_t smem_u32(const void* p) {
    uint32_t a;
    asm("{ .reg .u64 t; cvta.to.shared.u64 t, %1; cvt.u32.u64 %0, t; }"
        : "=r"(a) : "l"(p));
    return a;
}
#define SWZ128(off) ((off) ^ (((off) >> 3) & 0x70))

__device__ __forceinline__ void cp16(uint32_t saddr, const void* gaddr) {
    asm volatile("cp.async.cg.shared.global [%0], [%1], 16;\n"
                 :: "r"(saddr), "l"(gaddr));
}
__device__ __forceinline__ void cp_commit() {
    asm volatile("cp.async.commit_group;\n" ::: "memory");
}

__device__ __forceinline__ void ldsm_x4(uint32_t* r, uint32_t a) {
    asm volatile("ldmatrix.sync.aligned.m8n8.x4.shared.b16 {%0,%1,%2,%3}, [%4];"
                 : "=r"(r[0]), "=r"(r[1]), "=r"(r[2]), "=r"(r[3]) : "r"(a));
}

__device__ __forceinline__ void mma16816(float* d, const uint32_t* a,
                                         const uint32_t* b) {
    asm volatile(
        "mma.sync.aligned.m16n8k16.row.col.f32.f16.f16.f32 "
        "{%0,%1,%2,%3}, {%4,%5,%6,%7}, {%8,%9}, {%0,%1,%2,%3};\n"
        : "+f"(d[0]), "+f"(d[1]), "+f"(d[2]), "+f"(d[3])
        : "r"(a[0]), "r"(a[1]), "r"(a[2]), "r"(a[3]), "r"(b[0]), "r"(b[1]));
}

__device__ __forceinline__ float silu_f(float x) { return x / (1.0f + __expf(-x)); }

__device__ __forceinline__ void split_f16(float v, __half& h, __half& l) {
    h = __float2half_rn(v);
    l = __float2half_rn(v - __half2float(h));
}

// ---------------------------------------------------------------------------
// HMMA GEMM, CTA tile 128x256, 512 threads, warp tile 32x64 (4m x 4n warps),
// K-chunk 64, 2-stage ring with in-loader fp32->fp16 split for k < ksplit.
// ---------------------------------------------------------------------------
struct MP {
    const float*  Af;        // fp32 A source for k < ksplit
    int           ldaf;
    const __half *Ah, *Al;   // fp16 A source for k >= ksplit
    int           ldah, coffh;
    const __half *B;
    int M, K, ksplit, mstep;
    float *C0;
    __half *Oh, *Ol;
    const float *bias, *u, *vrow;
    // fused stage2a (EPI 2):
    const float *vw, *Wmix2;
    float *vvn2, *vw2;
    // fused stage2b (EPI 3):
    const float *W2b, *b2b, *pos;
    const int *batch;
    float *out;
    int nmol;
};

#define OFF_AL  16384
#define OFF_B   32768
#define OFF_F32 65536
#define STG     98304
#define SMEM_DYN (2 * STG)
#define SROW 264   // fp32 smem tile row stride (fused epilogues)

template <int EPI>
__global__ void __launch_bounds__(512, 1) gemm_mma(const MP p) {
    extern __shared__ __align__(1024) char smem[];
    const uint32_t sb = smem_u32(smem);
    const int tid  = threadIdx.x;
    const int wid  = tid >> 5;
    const int lane = tid & 31;
    const int wm   = wid >> 2;   // 0..3  (32-row slab)
    const int wn   = wid & 3;    // 0..3  (64-col slab)
    const int row0 = blockIdx.y * p.mstep;
    const int col0 = blockIdx.x * 256;

    // ldmatrix per-lane address components
    const int      rA0 = wm * 32 + (lane & 7) + ((lane >> 3) & 1) * 8;
    const uint32_t xA  = (uint32_t)(rA0 & 7) << 4;
    const uint32_t kA  = (uint32_t)(lane >> 4) * 16;
    const int      rB0 = wn * 64 + ((lane >> 4) * 8) + (lane & 7);
    const uint32_t xB  = (uint32_t)(rB0 & 7) << 4;
    const uint32_t kB  = (uint32_t)((lane >> 3) & 1) * 16;

    float acc[2][8][4];
#pragma unroll
    for (int i = 0; i < 2; i++)
#pragma unroll
        for (int j = 0; j < 8; j++)
#pragma unroll
            for (int q = 0; q < 4; q++) acc[i][j][q] = 0.f;

    const int NC = p.K >> 6;   // 64-wide K chunks

    auto load_chunk = [&](int kc, int s) {
        const uint32_t base = sb + s * STG;
        const int koff = kc * 64;
        if (koff < p.ksplit) {
            // fp32 A chunk -> staging buffer (linear, 256 B/row)
#pragma unroll
            for (int i = 0; i < 4; i++) {
                int idx = i * 512 + tid;
                int r = idx >> 4, u = idx & 15;
                int gr = row0 + r;
                if (gr > p.M - 1) gr = p.M - 1;
                cp16(base + OFF_F32 + (uint32_t)(r * 256 + u * 16),
                     p.Af + (size_t)gr * p.ldaf + koff + u * 4);
            }
        } else {
            // fp16 hi/lo A chunk -> swizzled tiles
#pragma unroll
            for (int i = 0; i < 2; i++) {
                int idx = i * 512 + tid;
                int r = idx >> 3, ch = idx & 7;
                uint32_t so = SWZ128((uint32_t)(r * 128 + ch * 16));
                int gr = row0 + r;
                if (gr > p.M - 1) gr = p.M - 1;
                size_t ga = (size_t)gr * p.ldah + p.coffh + (koff - p.ksplit) + ch * 8;
                cp16(base + so,          p.Ah + ga);
                cp16(base + OFF_AL + so, p.Al + ga);
            }
        }
#pragma unroll
        for (int i = 0; i < 4; i++) {
            int idx = i * 512 + tid;
            int r = idx >> 3, ch = idx & 7;
            uint32_t so = SWZ128((uint32_t)(r * 128 + ch * 16));
            size_t gb = (size_t)(col0 + r) * p.K + koff + ch * 8;
            cp16(base + OFF_B + so, p.B + gb);
        }
        cp_commit();
    };

    auto convert_stage = [&](int s) {
        char* stg = smem + s * STG;
#pragma unroll
        for (int i = 0; i < 2; i++) {
            int idx = i * 512 + tid;
            int r = idx >> 3, ch = idx & 7;
            const float* src = (const float*)(stg + OFF_F32 + r * 256 + ch * 32);
            float4 a = *(const float4*)(src);
            float4 b = *(const float4*)(src + 4);
            float f[8] = {a.x, a.y, a.z, a.w, b.x, b.y, b.z, b.w};
            __half hh[8], ll[8];
#pragma unroll
            for (int q = 0; q < 8; q++) split_f16(f[q], hh[q], ll[q]);
            uint32_t so = SWZ128((uint32_t)(r * 128 + ch * 16));
            *(uint4*)(stg + so)          = *(const uint4*)hh;
            *(uint4*)(stg + OFF_AL + so) = *(const uint4*)ll;
        }
    };

    load_chunk(0, 0);

    for (int c = 0; c < NC; c++) {
        const int s = c & 1;
        asm volatile("cp.async.wait_group 0;\n" ::: "memory");
        __syncthreads();
        if (c + 1 < NC) load_chunk(c + 1, s ^ 1);
        if ((c << 6) < p.ksplit) {
            convert_stage(s);
            __syncthreads();
        }

        const uint32_t base = sb + s * STG;
#pragma unroll
        for (int ks = 0; ks < 4; ks++) {
            const uint32_t kbA = ((uint32_t)(ks * 32) + kA) ^ xA;
            const uint32_t kbB = ((uint32_t)(ks * 32) + kB) ^ xB;
            uint32_t Ah4[2][4], Al4[2][4];
#pragma unroll
            for (int i = 0; i < 2; i++) {
                uint32_t ro = (uint32_t)(rA0 + i * 16) * 128;
                ldsm_x4(Ah4[i], base + ro + kbA);
                ldsm_x4(Al4[i], base + OFF_AL + ro + kbA);
            }
#pragma unroll
            for (int jp = 0; jp < 4; jp++) {
                uint32_t ro = (uint32_t)(rB0 + jp * 16) * 128;
                uint32_t bb[4];
                ldsm_x4(bb, base + OFF_B + ro + kbB);
#pragma unroll
                for (int i = 0; i < 2; i++) {
                    mma16816(acc[i][2 * jp],     Ah4[i], bb);
                    mma16816(acc[i][2 * jp + 1], Ah4[i], bb + 2);
                    mma16816(acc[i][2 * jp],     Al4[i], bb);
                    mma16816(acc[i][2 * jp + 1], Al4[i], bb + 2);
                }
            }
        }
    }
    __syncthreads();   // retire smem tiles before epilogue reuse

    // ---------------- epilogue ----------------
    const int mrow = lane >> 2;          // 0..7
    const int ncol = (lane & 3) * 2;     // 0,2,4,6
    float* st = (float*)smem;
    float* sW = st + 128 * SROW;

    if (EPI == 0 && col0 == 0) {
        // GEMM1 vV tile: stage accumulators, compute per-atom norms.
#pragma unroll
        for (int i = 0; i < 2; i++)
#pragma unroll
            for (int half = 0; half < 2; half++) {
                const int ml = wm * 32 + i * 16 + mrow + half * 8;
#pragma unroll
                for (int j = 0; j < 8; j++) {
                    const int nl = wn * 64 + j * 8 + ncol;
                    *(float2*)(st + (size_t)ml * SROW + nl) =
                        make_float2(acc[i][j][half * 2], acc[i][j][half * 2 + 1]);
                }
            }
        __syncthreads();
        const int atom0 = row0 / 3;
#pragma unroll 2
        for (int it = 0; it < 21; it++) {
            int idx = it * 512 + tid;
            int ai = idx >> 8, o = idx & 255;
            int a = atom0 + ai;
            if (3 * a + 2 < p.M) {
                float x = st[(size_t)(3 * ai)     * SROW + o];
                float y = st[(size_t)(3 * ai + 1) * SROW + o];
                float z = st[(size_t)(3 * ai + 2) * SROW + o];
                float v = sqrtf(x * x + y * y + z * z);
                __half h, l;
                split_f16(v, h, l);
                p.Oh[(size_t)a * 512 + 256 + o] = h;
                p.Ol[(size_t)a * 512 + 256 + o] = l;
            }
        }
        return;
    }

    if (EPI == 2 && col0 == 256) {
        // gate tile -> smem, then fused stage2a.
#pragma unroll
        for (int i = 0; i < 2; i++)
#pragma unroll
            for (int half = 0; half < 2; half++) {
                const int ml = wm * 32 + i * 16 + mrow + half * 8;
#pragma unroll
                for (int j = 0; j < 8; j++) {
                    const int nl = wn * 64 + j * 8 + ncol;
                    float v0 = acc[i][j][half * 2]     + p.bias[256 + nl];
                    float v1 = acc[i][j][half * 2 + 1] + p.bias[256 + nl + 1];
                    *(float2*)(st + (size_t)ml * SROW + nl) = make_float2(v0, v1);
                }
            }
        sW[tid] = p.Wmix2[tid];
        __syncthreads();
#pragma unroll 1
        for (int t = 0; t < 8; t++) {
            const int ml = wid * 8 + t;
            const int m  = row0 + ml;
            float t00 = 0, t01 = 0, t10 = 0, t11 = 0, t20 = 0, t21 = 0;
            if (m < p.M) {
                const float* vwp = p.vw + (size_t)3 * m * 256;
#pragma unroll
                for (int ii = 0; ii < 8; ii++) {
                    int o = lane + 32 * ii;
                    float ga = st[(size_t)ml * SROW + o];
                    float w0 = sW[2 * o], w1 = sW[2 * o + 1];
                    float q0 = ga * vwp[o];
                    float q1 = ga * vwp[256 + o];
                    float q2 = ga * vwp[512 + o];
                    t00 += q0 * w0; t01 += q0 * w1;
                    t10 += q1 * w0; t11 += q1 * w1;
                    t20 += q2 * w0; t21 += q2 * w1;
                }
            }
#pragma unroll
            for (int off = 16; off; off >>= 1) {
                t00 += __shfl_xor_sync(0xffffffffu, t00, off);
                t01 += __shfl_xor_sync(0xffffffffu, t01, off);
                t10 += __shfl_xor_sync(0xffffffffu, t10, off);
                t11 += __shfl_xor_sync(0xffffffffu, t11, off);
                t20 += __shfl_xor_sync(0xffffffffu, t20, off);
                t21 += __shfl_xor_sync(0xffffffffu, t21, off);
            }
            if (lane == 0 && m < p.M) {
                p.vvn2[m] = sqrtf(t00 * t00 + t10 * t10 + t20 * t20);
                p.vw2[3 * m + 0] = t01;
                p.vw2[3 * m + 1] = t11;
                p.vw2[3 * m + 2] = t21;
            }
        }
        return;
    }

    if (EPI == 3) {
        // h2 tile -> smem, then fused stage2b (final matvec + segment sums).
#pragma unroll
        for (int i = 0; i < 2; i++)
#pragma unroll
            for (int half = 0; half < 2; half++) {
                const int ml = wm * 32 + i * 16 + mrow + half * 8;
                const int m  = row0 + ml;
                float um = (m < p.M) ? p.u[m] : 0.f;
#pragma unroll
                for (int j = 0; j < 8; j++) {
                    const int nl = wn * 64 + j * 8 + ncol;
                    float v0 = silu_f(acc[i][j][half * 2] +
                                      um * p.vrow[nl] + p.bias[nl]);
                    float v1 = silu_f(acc[i][j][half * 2 + 1] +
                                      um * p.vrow[nl + 1] + p.bias[nl + 1]);
                    *(float2*)(st + (size_t)ml * SROW + nl) = make_float2(v0, v1);
                }
            }
        sW[tid] = p.W2b[tid];
        if (tid == 0) { sW[512] = p.b2b[0]; sW[513] = p.b2b[1]; }
        __syncthreads();
#pragma unroll 1
        for (int t = 0; t < 8; t++) {
            const int ml = wid * 8 + t;
            const int m  = row0 + ml;
            float x0 = 0, x1 = 0;
            if (m < p.M) {
#pragma unroll
                for (int ii = 0; ii < 8; ii++) {
                    int k = lane + 32 * ii;
                    float hv = st[(size_t)ml * SROW + k];
                    x0 += hv * sW[2 * k];
                    x1 += hv * sW[2 * k + 1];
                }
            }
#pragma unroll
            for (int off = 16; off; off >>= 1) {
                x0 += __shfl_xor_sync(0xffffffffu, x0, off);
                x1 += __shfl_xor_sync(0xffffffffu, x1, off);
            }
            if (lane == 0 && m < p.M) {
                float charge = x0 + sW[512];
                float gate2  = x1 + sW[513];
                int b = p.batch[m];
#pragma unroll
                for (int c = 0; c < 3; c++) {
                    float v2 = gate2 * p.vw2[3 * m + c];
                    float y  = v2 + p.pos[3 * m + c] * charge;
                    atomicAdd(&p.out[(size_t)b * 3 + c], y);
                    atomicAdd(&p.out[(size_t)p.nmol * 3 + (size_t)b * 3 + c], v2);
                }
            }
        }
        return;
    }

    // Generic register epilogues (EPI 0 col 256, EPI 1, EPI 2 col 0)
#pragma unroll
    for (int i = 0; i < 2; i++) {
        const int mbase = row0 + wm * 32 + i * 16 + mrow;
#pragma unroll
        for (int half = 0; half < 2; half++) {
            const int m = mbase + half * 8;
            if (m >= p.M) continue;
#pragma unroll
            for (int j = 0; j < 8; j++) {
                const int n = col0 + wn * 64 + j * 8 + ncol;
                float v0 = acc[i][j][half * 2 + 0];
                float v1 = acc[i][j][half * 2 + 1];
                if (EPI == 0) {
                    // GEMM1 vW tile: fp32 -> C0 (ld 256)
                    *(float2*)(p.C0 + (size_t)m * 256 + (n - 256)) = make_float2(v0, v1);
                } else {
                    // EPI 1, or EPI 2 col 0: silu(v+bias) -> fp16 hi/lo
                    v0 = silu_f(v0 + p.bias[n]);
                    v1 = silu_f(v1 + p.bias[n + 1]);
                    __half h0, l0, h1, l1;
                    split_f16(v0, h0, l0);
                    split_f16(v1, h1, l1);
                    *(__half2*)(p.Oh + (size_t)m * 256 + n) = __half2(h0, h1);
                    *(__half2*)(p.Ol + (size_t)m * 256 + n) = __half2(l0, l1);
                }
            }
        }
    }
}

// ---------------------------------------------------------------------------
// all four weight transposes (fp32 [K,N] -> fp16 [N,K]) in one launch
// ---------------------------------------------------------------------------
struct WT {
    const float *W1, *W2, *W3, *W4;
    __half *t1, *t2, *t3, *t4;
};
__global__ void wt_conv_all(const WT w) {
    int idx = blockIdx.x * blockDim.x + threadIdx.x;
    if (idx < 131072) {                       // Wmix1: K=256, N=512
        int k = idx >> 9, n = idx & 511;
        w.t1[(size_t)n * 256 + k] = __float2half_rn(w.W1[idx]);
    } else if (idx < 262144) {                // W1a: K=512, N=256
        int r = idx - 131072;
        int k = r >> 8, n = r & 255;
        w.t2[(size_t)n * 512 + k] = __float2half_rn(w.W2[r]);
    } else if (idx < 393216) {                // W2a: K=256, N=512
        int r = idx - 262144;
        int k = r >> 9, n = r & 511;
        w.t3[(size_t)n * 256 + k] = __float2half_rn(w.W3[r]);
    } else if (idx < 458752) {                // W1b[:256]: K=256, N=256
        int r = idx - 393216;
        int k = r >> 8, n = r & 255;
        w.t4[(size_t)n * 256 + k] = __float2half_rn(w.W4[r]);
    }
}

// ---------------------------------------------------------------------------
extern "C" void kernel_launch(void* const* d_in, const int* in_sizes, int n_in,
                              void* d_out, int out_size) {
    const float* pos   = (const float*)d_in[0];
    const float* l0    = (const float*)d_in[1];
    const float* l1    = (const float*)d_in[2];
    const int*   batch = (const int*)d_in[3];
    const float* Wmix1 = (const float*)d_in[4];
    const float* W1a   = (const float*)d_in[5];
    const float* b1a   = (const float*)d_in[6];
    const float* W2a   = (const float*)d_in[7];
    const float* b2a   = (const float*)d_in[8];
    const float* Wmix2 = (const float*)d_in[9];
    const float* W1b   = (const float*)d_in[10];
    const float* b1b   = (const float*)d_in[11];
    const float* W2b   = (const float*)d_in[12];
    const float* b2b   = (const float*)d_in[13];

    const int natoms = in_sizes[3];
    const int nmol   = out_size / 6;
    float* out = (float*)d_out;

    float *vw, *vvn2, *vw2;
    __half *a2h, *a2l, *a3h, *a3l, *a4h, *a4l;
    __half *bt1, *bt2, *bt3, *bt4;
    cudaGetSymbolAddress((void**)&vw,   g_vw);
    cudaGetSymbolAddress((void**)&vvn2, g_vvn2);
    cudaGetSymbolAddress((void**)&vw2,  g_vw2);
    cudaGetSymbolAddress((void**)&a2h, g_a2h);  cudaGetSymbolAddress((void**)&a2l, g_a2l);
    cudaGetSymbolAddress((void**)&a3h, g_a3h);  cudaGetSymbolAddress((void**)&a3l, g_a3l);
    cudaGetSymbolAddress((void**)&a4h, g_a4h);  cudaGetSymbolAddress((void**)&a4l, g_a4l);
    cudaGetSymbolAddress((void**)&bt1, g_bt1);
    cudaGetSymbolAddress((void**)&bt2, g_bt2);
    cudaGetSymbolAddress((void**)&bt3, g_bt3);
    cudaGetSymbolAddress((void**)&bt4, g_bt4);

    cudaFuncSetAttribute(gemm_mma<0>, cudaFuncAttributeMaxDynamicSharedMemorySize, SMEM_DYN);
    cudaFuncSetAttribute(gemm_mma<1>, cudaFuncAttributeMaxDynamicSharedMemorySize, SMEM_DYN);
    cudaFuncSetAttribute(gemm_mma<2>, cudaFuncAttributeMaxDynamicSharedMemorySize, SMEM_DYN);
    cudaFuncSetAttribute(gemm_mma<3>, cudaFuncAttributeMaxDynamicSharedMemorySize, SMEM_DYN);

    cudaMemsetAsync(d_out, 0, (size_t)out_size * sizeof(float));

    const int M1  = 3 * natoms;
    const int mt1 = (M1 + 125) / 126;          // GEMM1: 126-row tiles (42 atoms)
    const int mt  = (natoms + 127) / 128;

    // all weight transposes in one launch
    {
        WT w = {Wmix1, W1a, W2a, W1b, bt1, bt2, bt3, bt4};
        wt_conv_all<<<(458752 + 255) / 256, 256>>>(w);
    }

    // GEMM1: vmix = l1 @ Wmix1 (3N x 512), A loaded fp32 + split in-kernel.
    // col tile 0 -> fused vVn norms into a2 cols 256:512; col tile 1 -> vW.
    {
        MP p = {};
        p.Af = l1; p.ldaf = 256; p.ksplit = 256;
        p.Ah = a2h; p.Al = a2l; p.ldah = 512; p.coffh = 0;   // unused
        p.B = bt1; p.M = M1; p.K = 256; p.mstep = 126;
        p.C0 = vw; p.Oh = a2h; p.Ol = a2l;
        gemm_mma<0><<<dim3(2, mt1), 512, SMEM_DYN>>>(p);
    }

    // GEMM2: h = silu([l0 | vVn] @ W1a + b1a) -> a3 (hi/lo).
    {
        MP p = {};
        p.Af = l0; p.ldaf = 256; p.ksplit = 256;
        p.Ah = a2h; p.Al = a2l; p.ldah = 512; p.coffh = 256;
        p.B = bt2; p.M = natoms; p.K = 512; p.mstep = 128;
        p.Oh = a3h; p.Ol = a3l; p.bias = b1a;
        gemm_mma<1><<<dim3(1, mt), 512, SMEM_DYN>>>(p);
    }

    // GEMM3: x = h @ W2a + b2a. col tile 0: s1 = silu -> a4 hi/lo;
    // col tile 1: gate -> fused stage2a (vvn2, vw2).
    {
        MP p = {};
        p.Af = nullptr; p.ldaf = 256; p.ksplit = 0;
        p.Ah = a3h; p.Al = a3l; p.ldah = 256; p.coffh = 0;
        p.B = bt3; p.M = natoms; p.K = 256; p.mstep = 128;
        p.Oh = a4h; p.Ol = a4l; p.bias = b2a;
        p.vw = vw; p.Wmix2 = Wmix2; p.vvn2 = vvn2; p.vw2 = vw2;
        gemm_mma<2><<<dim3(2, mt), 512, SMEM_DYN>>>(p);
    }

    // GEMM4: h2 = silu(s1 @ W1b[:256] + vvn2*W1b[256] + b1b) -> fused
    // stage2b: charge/gate2 matvec + gating + segment atomics.
    {
        MP p = {};
        p.Af = nullptr; p.ldaf = 256; p.ksplit = 0;
        p.Ah = a4h; p.Al = a4l; p.ldah = 256; p.coffh = 0;
        p.B = bt4; p.M = natoms; p.K = 256; p.mstep = 128;
        p.bias = b1b; p.u = vvn2; p.vrow = W1b + 256 * 256;
        p.W2b = W2b; p.b2b = b2b; p.pos = pos; p.batch = batch;
        p.vw2 = vw2; p.out = out; p.nmol = nmol;
        gemm_mma<3><<<dim3(1, mt), 512, SMEM_DYN>>>(p);
    }
}